// round 3
// baseline (speedup 1.0000x reference)
#include <cuda_runtime.h>
#include <cuda_bf16.h>
#include <math.h>

// ---------------- problem constants ----------------
#define BATCH   32
#define NPATCH  196
#define TOK     (BATCH * NPATCH)   // 6272
#define DMODEL  768
#define NHEAD   12
#define HDIM    64
#define NLAYER  12
#define HIDDEN  3072
#define QKVN    (3 * DMODEL)       // 2304
#define IMG     224
#define PSZ     16
#define GRID_   14

// ---------------- scratch (no allocations allowed) ----------------
__device__ float g_xp [(size_t)TOK * DMODEL];
__device__ float g_wpe[(size_t)DMODEL * DMODEL];
__device__ float g_h  [(size_t)TOK * DMODEL];
__device__ float g_y  [(size_t)TOK * DMODEL];
__device__ float g_qkv[(size_t)TOK * QKVN];
__device__ float g_o  [(size_t)TOK * DMODEL];
__device__ float g_act[(size_t)TOK * HIDDEN];

// ---------------- patchify: x[B,3,224,224] -> xp[TOK, 768] ----------------
__global__ void patch_kernel(const float* __restrict__ x, float* __restrict__ xp) {
    int idx = blockIdx.x * blockDim.x + threadIdx.x;
    if (idx >= TOK * DMODEL) return;
    int t = idx / DMODEL;
    int f = idx - t * DMODEL;          // f = c*256 + py*16 + px
    int b = t / NPATCH;
    int p = t - b * NPATCH;
    int gy = p / GRID_, gx = p - gy * GRID_;
    int c  = f >> 8;
    int py = (f >> 4) & 15;
    int px = f & 15;
    xp[idx] = x[(((size_t)b * 3 + c) * IMG + gy * PSZ + py) * IMG + gx * PSZ + px];
}

// ---------------- transpose conv_w (D x D) -> wpe[k][d] ----------------
__global__ void transpose_kernel(const float* __restrict__ src, float* __restrict__ dst) {
    __shared__ float tile[32][33];
    int bx = blockIdx.x * 32;   // k tile
    int by = blockIdx.y * 32;   // d tile
    for (int i = threadIdx.y; i < 32; i += 8)
        tile[i][threadIdx.x] = src[(size_t)(by + i) * DMODEL + bx + threadIdx.x];
    __syncthreads();
    for (int i = threadIdx.y; i < 32; i += 8)
        dst[(size_t)(bx + i) * DMODEL + by + threadIdx.x] = tile[threadIdx.x][i];
}

// ---------------- generic tiled SGEMM: C[M,N] = A[M,K] @ B[K,N] + epilogue ----------------
// OP 0: + bias[n]
// OP 1: + bias[n] + res[m*N+n]         (residual add, may alias C)
// OP 2: + bias[n], then exact GELU
// OP 3: + bias[n] + res[(m%196)*N+n]   (pos-embed add)
// Requires: M%64==0, N%64==0, K%16==0  (true for all call sites)
#define BM 64
#define BN 64
#define BKK 16

template <int OP>
__global__ void gemm_kernel(const float* __restrict__ A, const float* __restrict__ B,
                            const float* __restrict__ bias, const float* __restrict__ res,
                            float* __restrict__ C, int M, int N, int K) {
    __shared__ float As[BKK][BM + 4];
    __shared__ float Bs[BKK][BN];
    int tid = threadIdx.x;                 // 256 threads
    int ty = tid >> 4, tx = tid & 15;
    int m0 = blockIdx.y * BM, n0 = blockIdx.x * BN;

    int ar = tid >> 2;                     // 0..63
    int ac = (tid & 3) * 4;                // 0,4,8,12
    int br = tid >> 4;                     // 0..15
    int bc = (tid & 15) * 4;               // 0..60

    float acc[4][4] = {};
    for (int k0 = 0; k0 < K; k0 += BKK) {
        float4 av = *(const float4*)(A + (size_t)(m0 + ar) * K + k0 + ac);
        As[ac + 0][ar] = av.x; As[ac + 1][ar] = av.y;
        As[ac + 2][ar] = av.z; As[ac + 3][ar] = av.w;
        *(float4*)(&Bs[br][bc]) = *(const float4*)(B + (size_t)(k0 + br) * N + n0 + bc);
        __syncthreads();
#pragma unroll
        for (int kk = 0; kk < BKK; kk++) {
            float a[4], b[4];
#pragma unroll
            for (int i = 0; i < 4; i++) a[i] = As[kk][ty * 4 + i];
#pragma unroll
            for (int j = 0; j < 4; j++) b[j] = Bs[kk][tx * 4 + j];
#pragma unroll
            for (int i = 0; i < 4; i++)
#pragma unroll
                for (int j = 0; j < 4; j++)
                    acc[i][j] += a[i] * b[j];
        }
        __syncthreads();
    }
#pragma unroll
    for (int i = 0; i < 4; i++) {
        int m = m0 + ty * 4 + i;
#pragma unroll
        for (int j = 0; j < 4; j++) {
            int n = n0 + tx * 4 + j;
            float v = acc[i][j] + bias[n];
            if (OP == 1) v += res[(size_t)m * N + n];
            if (OP == 2) v = 0.5f * v * (1.0f + erff(v * 0.70710678118654752f));
            if (OP == 3) v += res[(size_t)(m % NPATCH) * N + n];
            C[(size_t)m * N + n] = v;
        }
    }
}

// ---------------- attention: per (b, head) block ----------------
// qkv layout: [t][s*768 + h*64 + d], s in {q=0,k=1,v=2}
#define KROW 68                      // 64 + 4 pad (conflict-free float4 LDS)
#define SMEM_ATTN ((2 * 196 * KROW + 8 * KROW + 8 * 200) * 4)

__global__ void attn_kernel(const float* __restrict__ qkv, float* __restrict__ o) {
    extern __shared__ float sm[];
    float* Ks = sm;                        // 196*68
    float* Vs = Ks + 196 * KROW;           // 196*68
    float* Qs = Vs + 196 * KROW;           // 8*68
    float* Ps = Qs + 8 * KROW;             // 8*200

    int bh = blockIdx.x;
    int b = bh / NHEAD, h = bh - b * NHEAD;
    int tid = threadIdx.x;                 // 256
    const float* base = qkv + (size_t)b * NPATCH * QKVN + h * HDIM;

    // load K and V tiles (float4 granularity)
    for (int i = tid; i < NPATCH * 16; i += 256) {
        int row = i >> 4, c4 = (i & 15) * 4;
        *(float4*)(&Ks[row * KROW + c4]) =
            *(const float4*)(base + (size_t)row * QKVN + DMODEL + c4);
        *(float4*)(&Vs[row * KROW + c4]) =
            *(const float4*)(base + (size_t)row * QKVN + 2 * DMODEL + c4);
    }
    __syncthreads();

    int w = tid >> 5, lane = tid & 31;
    const float scale = 0.125f;            // 64^-0.5

    for (int q = w; q < NPATCH; q += 8) {
        // stage Q row into smem
        for (int d = lane; d < HDIM; d += 32)
            Qs[w * KROW + d] = base[(size_t)q * QKVN + d];
        __syncwarp();

        float sc[7];
        float mx = -1e30f;
#pragma unroll
        for (int kk = 0; kk < 7; kk++) {
            int kidx = lane + kk * 32;
            float s = -1e30f;
            if (kidx < NPATCH) {
                const float4* kr = (const float4*)(&Ks[kidx * KROW]);
                const float4* qr = (const float4*)(&Qs[w * KROW]);
                float acc = 0.f;
#pragma unroll
                for (int d4 = 0; d4 < 16; d4++) {
                    float4 kv = kr[d4], qv = qr[d4];
                    acc += kv.x * qv.x + kv.y * qv.y + kv.z * qv.z + kv.w * qv.w;
                }
                s = acc * scale;
            }
            sc[kk] = s;
            mx = fmaxf(mx, s);
        }
#pragma unroll
        for (int off = 16; off; off >>= 1)
            mx = fmaxf(mx, __shfl_xor_sync(0xffffffffu, mx, off));

        float sum = 0.f;
#pragma unroll
        for (int kk = 0; kk < 7; kk++) {
            int kidx = lane + kk * 32;
            float e = (kidx < NPATCH) ? __expf(sc[kk] - mx) : 0.f;
            sc[kk] = e;
            sum += e;
        }
#pragma unroll
        for (int off = 16; off; off >>= 1)
            sum += __shfl_xor_sync(0xffffffffu, sum, off);
        float inv = 1.f / sum;
#pragma unroll
        for (int kk = 0; kk < 7; kk++) {
            int kidx = lane + kk * 32;
            if (kidx < NPATCH) Ps[w * 200 + kidx] = sc[kk] * inv;
        }
        __syncwarp();

        // O = P @ V ; lane handles d = lane and lane+32
        float o0 = 0.f, o1 = 0.f;
        for (int k = 0; k < NPATCH; k++) {
            float p = Ps[w * 200 + k];
            o0 += p * Vs[k * KROW + lane];
            o1 += p * Vs[k * KROW + lane + 32];
        }
        size_t t = (size_t)b * NPATCH + q;
        o[t * DMODEL + h * HDIM + lane]      = o0;
        o[t * DMODEL + h * HDIM + lane + 32] = o1;
        __syncwarp();
    }
}

// ---------------- layernorm: one block (256 thr) per token row of 768 ----------------
__global__ void ln_kernel(const float* __restrict__ x, const float* __restrict__ w,
                          const float* __restrict__ bb, float* __restrict__ y) {
    int t = blockIdx.x;
    const float* xr = x + (size_t)t * DMODEL;
    int tid = threadIdx.x;
    float v[3];
    float s = 0.f, ss = 0.f;
#pragma unroll
    for (int i = 0; i < 3; i++) {
        v[i] = xr[tid + i * 256];
        s += v[i];
        ss += v[i] * v[i];
    }
    __shared__ float redS[8], redQ[8];
#pragma unroll
    for (int off = 16; off; off >>= 1) {
        s  += __shfl_xor_sync(0xffffffffu, s,  off);
        ss += __shfl_xor_sync(0xffffffffu, ss, off);
    }
    if ((tid & 31) == 0) { redS[tid >> 5] = s; redQ[tid >> 5] = ss; }
    __syncthreads();
    if (tid == 0) {
        float a = 0.f, b2 = 0.f;
#pragma unroll
        for (int i = 0; i < 8; i++) { a += redS[i]; b2 += redQ[i]; }
        float mean = a * (1.0f / DMODEL);
        float var = b2 * (1.0f / DMODEL) - mean * mean;
        redS[0] = mean;
        redQ[0] = rsqrtf(var + 1e-5f);
    }
    __syncthreads();
    float mean = redS[0], rstd = redQ[0];
    float* yr = y + (size_t)t * DMODEL;
#pragma unroll
    for (int i = 0; i < 3; i++) {
        int c = tid + i * 256;
        yr[c] = (v[i] - mean) * rstd * w[c] + bb[c];
    }
}

// ---------------- launch ----------------
extern "C" void kernel_launch(void* const* d_in, const int* in_sizes, int n_in,
                              void* d_out, int out_size) {
    const float* x      = (const float*)d_in[0];
    const float* conv_w = (const float*)d_in[1];
    const float* conv_b = (const float*)d_in[2];
    const float* pos    = (const float*)d_in[3];
    const float* ln1w   = (const float*)d_in[4];
    const float* ln1b   = (const float*)d_in[5];
    const float* qkvw   = (const float*)d_in[6];
    const float* qkvb   = (const float*)d_in[7];
    const float* projw  = (const float*)d_in[8];
    const float* projb  = (const float*)d_in[9];
    const float* ln2w   = (const float*)d_in[10];
    const float* ln2b   = (const float*)d_in[11];
    const float* f1w    = (const float*)d_in[12];
    const float* f1b    = (const float*)d_in[13];
    const float* f2w    = (const float*)d_in[14];
    const float* f2b    = (const float*)d_in[15];
    const float* lnfw   = (const float*)d_in[16];
    const float* lnfb   = (const float*)d_in[17];
    float* out = (float*)d_out;

    float *xp, *wpe, *h, *y, *qkv, *o, *act;
    cudaGetSymbolAddress((void**)&xp,  g_xp);
    cudaGetSymbolAddress((void**)&wpe, g_wpe);
    cudaGetSymbolAddress((void**)&h,   g_h);
    cudaGetSymbolAddress((void**)&y,   g_y);
    cudaGetSymbolAddress((void**)&qkv, g_qkv);
    cudaGetSymbolAddress((void**)&o,   g_o);
    cudaGetSymbolAddress((void**)&act, g_act);

    cudaFuncSetAttribute(attn_kernel, cudaFuncAttributeMaxDynamicSharedMemorySize, SMEM_ATTN);

    // patchify + patch-embed GEMM (+bias +pos_embed)
    patch_kernel<<<(TOK * DMODEL + 255) / 256, 256>>>(x, xp);
    transpose_kernel<<<dim3(24, 24), dim3(32, 8)>>>(conv_w, wpe);
    gemm_kernel<3><<<dim3(DMODEL / BN, TOK / BM), 256>>>(xp, wpe, conv_b, pos, h,
                                                         TOK, DMODEL, DMODEL);

    for (int l = 0; l < NLAYER; l++) {
        ln_kernel<<<TOK, 256>>>(h, ln1w + (size_t)l * DMODEL, ln1b + (size_t)l * DMODEL, y);
        gemm_kernel<0><<<dim3(QKVN / BN, TOK / BM), 256>>>(
            y, qkvw + (size_t)l * DMODEL * QKVN, qkvb + (size_t)l * QKVN, nullptr, qkv,
            TOK, QKVN, DMODEL);
        attn_kernel<<<BATCH * NHEAD, 256, SMEM_ATTN>>>(qkv, o);
        gemm_kernel<1><<<dim3(DMODEL / BN, TOK / BM), 256>>>(
            o, projw + (size_t)l * DMODEL * DMODEL, projb + (size_t)l * DMODEL, h, h,
            TOK, DMODEL, DMODEL);
        ln_kernel<<<TOK, 256>>>(h, ln2w + (size_t)l * DMODEL, ln2b + (size_t)l * DMODEL, y);
        gemm_kernel<2><<<dim3(HIDDEN / BN, TOK / BM), 256>>>(
            y, f1w + (size_t)l * DMODEL * HIDDEN, f1b + (size_t)l * HIDDEN, nullptr, act,
            TOK, HIDDEN, DMODEL);
        gemm_kernel<1><<<dim3(DMODEL / BN, TOK / BM), 256>>>(
            act, f2w + (size_t)l * HIDDEN * DMODEL, f2b + (size_t)l * DMODEL, h, h,
            TOK, DMODEL, HIDDEN);
    }
    ln_kernel<<<TOK, 256>>>(h, lnfw, lnfb, out);
}

// round 6
// speedup vs baseline: 2.9684x; 2.9684x over previous
#include <cuda_runtime.h>
#include <cuda_bf16.h>
#include <math.h>
#include <stdint.h>

// ---------------- problem constants ----------------
#define BATCH   32
#define NPATCH  196
#define TOK     (BATCH * NPATCH)   // 6272
#define DMODEL  768
#define NHEAD   12
#define HDIM    64
#define NLAYER  12
#define HIDDEN  3072
#define QKVN    (3 * DMODEL)       // 2304
#define IMG     224
#define PSZ     16
#define GRID_   14

// ---------------- scratch (no allocations allowed) ----------------
__device__ float g_xp [(size_t)TOK * DMODEL];
__device__ float g_wpe[(size_t)DMODEL * DMODEL];
__device__ float g_h  [(size_t)TOK * DMODEL];
__device__ float g_y  [(size_t)TOK * DMODEL];
__device__ float g_qkv[(size_t)TOK * QKVN];
__device__ float g_o  [(size_t)TOK * DMODEL];
__device__ float g_act[(size_t)TOK * HIDDEN];
// tf32-rounded weights (RNA) — unbiased rounding keeps GEMM error ~1e-5
__device__ float g_qkvw[(size_t)NLAYER * DMODEL * QKVN];
__device__ float g_projw[(size_t)NLAYER * DMODEL * DMODEL];
__device__ float g_f1w [(size_t)NLAYER * DMODEL * HIDDEN];
__device__ float g_f2w [(size_t)NLAYER * HIDDEN * DMODEL];

// ---------------- tf32 round-to-nearest ----------------
__device__ __forceinline__ float rtf32(float x) {
    uint32_t u;
    asm("cvt.rna.tf32.f32 %0, %1;" : "=r"(u) : "f"(x));
    return __uint_as_float(u);
}

// ---------------- weight rounding (float4 grid-stride) ----------------
__global__ void round_kernel(const float* __restrict__ src, float* __restrict__ dst, int n4) {
    int i = blockIdx.x * blockDim.x + threadIdx.x;
    if (i >= n4) return;
    float4 v = ((const float4*)src)[i];
    v.x = rtf32(v.x); v.y = rtf32(v.y); v.z = rtf32(v.z); v.w = rtf32(v.w);
    ((float4*)dst)[i] = v;
}

// ---------------- patchify: x[B,3,224,224] -> xp[TOK, 768] (tf32-rounded) ----------------
__global__ void patch_kernel(const float* __restrict__ x, float* __restrict__ xp) {
    int idx = blockIdx.x * blockDim.x + threadIdx.x;
    if (idx >= TOK * DMODEL) return;
    int t = idx / DMODEL;
    int f = idx - t * DMODEL;
    int b = t / NPATCH;
    int p = t - b * NPATCH;
    int gy = p / GRID_, gx = p - gy * GRID_;
    int c  = f >> 8;
    int py = (f >> 4) & 15;
    int px = f & 15;
    xp[idx] = rtf32(x[(((size_t)b * 3 + c) * IMG + gy * PSZ + py) * IMG + gx * PSZ + px]);
}

// ---------------- transpose conv_w (D x D) -> wpe[k][d], tf32-rounded ----------------
__global__ void transpose_kernel(const float* __restrict__ src, float* __restrict__ dst) {
    __shared__ float tile[32][33];
    int bx = blockIdx.x * 32;
    int by = blockIdx.y * 32;
    for (int i = threadIdx.y; i < 32; i += 8)
        tile[i][threadIdx.x] = src[(size_t)(by + i) * DMODEL + bx + threadIdx.x];
    __syncthreads();
    for (int i = threadIdx.y; i < 32; i += 8)
        dst[(size_t)(bx + i) * DMODEL + by + threadIdx.x] = rtf32(tile[threadIdx.x][i]);
}

// ---------------- TF32 tensor-core GEMM ----------------
// C[M,N] = A[M,K] @ B[K,N] + epilogue, A/B already tf32-rounded fp32.
// CTA tile 128x128x32, 8 warps (2x4), warp tile 64x32, mma m16n8k8.
// OP 0: +bias ; OP 1: +bias+res[m*N+n] ; OP 2: +bias then GELU (round output) ;
// OP 3: +bias + res[(m%196)*N+n]
#define AS_STR 36     // 32 + 4 pad  -> conflict-free a-frag LDS
#define BS_STR 136    // 128 + 8 pad -> conflict-free b-frag LDS
#define STAGE_F (128 * AS_STR + 32 * BS_STR)   // 4608 + 4352 = 8960 floats
#define GEMM_SMEM (2 * STAGE_F * 4)            // 71680 bytes

__device__ __forceinline__ void cpasync16(void* dst, const void* src) {
    uint32_t d = (uint32_t)__cvta_generic_to_shared(dst);
    asm volatile("cp.async.cg.shared.global [%0], [%1], 16;" :: "r"(d), "l"(src));
}
__device__ __forceinline__ void mma_tf32(float* c, const uint32_t* a, const uint32_t* b) {
    asm volatile(
        "mma.sync.aligned.m16n8k8.row.col.f32.tf32.tf32.f32 "
        "{%0,%1,%2,%3}, {%4,%5,%6,%7}, {%8,%9}, {%0,%1,%2,%3};"
        : "+f"(c[0]), "+f"(c[1]), "+f"(c[2]), "+f"(c[3])
        : "r"(a[0]), "r"(a[1]), "r"(a[2]), "r"(a[3]), "r"(b[0]), "r"(b[1]));
}

template <int OP>
__global__ void __launch_bounds__(256, 2)
gemm_tf32(const float* __restrict__ A, const float* __restrict__ B,
          const float* __restrict__ bias, const float* __restrict__ res,
          float* __restrict__ C, int M, int N, int K) {
    extern __shared__ float sm[];
    const int tid = threadIdx.x;
    const int m0 = blockIdx.y * 128, n0 = blockIdx.x * 128;
    const int warp = tid >> 5, lane = tid & 31;
    const int wm = warp >> 2, wn = warp & 3;     // 2 x 4 warp grid
    const int g = lane >> 2, tg = lane & 3;

    const int arow = tid >> 3, acol = (tid & 7) * 4;     // A: 128 rows x 8 chunks
    const int brow = tid >> 5, bcol = (tid & 31) * 4;    // B: 32 rows x 32 chunks

    float acc[4][4][4];
#pragma unroll
    for (int i = 0; i < 4; i++)
#pragma unroll
        for (int j = 0; j < 4; j++)
#pragma unroll
            for (int c = 0; c < 4; c++) acc[i][j][c] = 0.f;

    const int nIter = K >> 5;

    // ---- prologue: stage 0 ----
    {
        float* As = sm; float* Bs = sm + 128 * AS_STR;
        const float* Ag = A + (size_t)m0 * K;
        const float* Bg = B + n0;
#pragma unroll
        for (int i = 0; i < 4; i++) {
            int r = arow + i * 32;
            cpasync16(&As[r * AS_STR + acol], Ag + (size_t)r * K + acol);
        }
#pragma unroll
        for (int i = 0; i < 4; i++) {
            int r = brow + i * 8;
            cpasync16(&Bs[r * BS_STR + bcol], Bg + (size_t)r * N + bcol);
        }
        asm volatile("cp.async.commit_group;");
    }

    for (int it = 0; it < nIter; it++) {
        if (it + 1 < nIter) {
            int s = (it + 1) & 1;
            float* As = sm + s * STAGE_F;
            float* Bs = As + 128 * AS_STR;
            int k0 = (it + 1) * 32;
            const float* Ag = A + (size_t)m0 * K + k0;
            const float* Bg = B + (size_t)k0 * N + n0;
#pragma unroll
            for (int i = 0; i < 4; i++) {
                int r = arow + i * 32;
                cpasync16(&As[r * AS_STR + acol], Ag + (size_t)r * K + acol);
            }
#pragma unroll
            for (int i = 0; i < 4; i++) {
                int r = brow + i * 8;
                cpasync16(&Bs[r * BS_STR + bcol], Bg + (size_t)r * N + bcol);
            }
            asm volatile("cp.async.commit_group;");
            asm volatile("cp.async.wait_group 1;");
        } else {
            asm volatile("cp.async.wait_group 0;");
        }
        __syncthreads();

        const float* As = sm + (it & 1) * STAGE_F;
        const float* Bs = As + 128 * AS_STR;
#pragma unroll
        for (int kk = 0; kk < 4; kk++) {
            uint32_t a[4][4], b[4][2];
#pragma unroll
            for (int mi = 0; mi < 4; mi++) {
                const float* p = As + (wm * 64 + mi * 16 + g) * AS_STR + kk * 8 + tg;
                a[mi][0] = __float_as_uint(p[0]);
                a[mi][1] = __float_as_uint(p[8 * AS_STR]);
                a[mi][2] = __float_as_uint(p[4]);
                a[mi][3] = __float_as_uint(p[8 * AS_STR + 4]);
            }
#pragma unroll
            for (int ni = 0; ni < 4; ni++) {
                const float* p = Bs + (kk * 8 + tg) * BS_STR + wn * 32 + ni * 8 + g;
                b[ni][0] = __float_as_uint(p[0]);
                b[ni][1] = __float_as_uint(p[4 * BS_STR]);
            }
#pragma unroll
            for (int mi = 0; mi < 4; mi++)
#pragma unroll
                for (int ni = 0; ni < 4; ni++)
                    mma_tf32(acc[mi][ni], a[mi], b[ni]);
        }
        __syncthreads();
    }

    // ---- epilogue ----
#pragma unroll
    for (int mi = 0; mi < 4; mi++) {
        int mb = m0 + wm * 64 + mi * 16 + g;
#pragma unroll
        for (int ni = 0; ni < 4; ni++) {
            int n = n0 + wn * 32 + ni * 8 + tg * 2;
            float bi0 = bias[n], bi1 = bias[n + 1];
#pragma unroll
            for (int half = 0; half < 2; half++) {
                int m = mb + half * 8;
                float v0 = acc[mi][ni][half * 2 + 0] + bi0;
                float v1 = acc[mi][ni][half * 2 + 1] + bi1;
                if (OP == 1) {
                    v0 += res[(size_t)m * N + n];
                    v1 += res[(size_t)m * N + n + 1];
                }
                if (OP == 2) {
                    v0 = 0.5f * v0 * (1.0f + erff(v0 * 0.70710678118654752f));
                    v1 = 0.5f * v1 * (1.0f + erff(v1 * 0.70710678118654752f));
                    v0 = rtf32(v0); v1 = rtf32(v1);   // feeds fc2 as A operand
                }
                if (OP == 3) {
                    v0 += res[(size_t)(m % NPATCH) * N + n];
                    v1 += res[(size_t)(m % NPATCH) * N + n + 1];
                }
                C[(size_t)m * N + n]     = v0;
                C[(size_t)m * N + n + 1] = v1;
            }
        }
    }
}

// ---------------- attention: per (b, head) block (fp32) ----------------
#define KROW 68
#define SMEM_ATTN ((2 * 196 * KROW + 8 * KROW + 8 * 200) * 4)

__global__ void attn_kernel(const float* __restrict__ qkv, float* __restrict__ o) {
    extern __shared__ float smA[];
    float* Ks = smA;
    float* Vs = Ks + 196 * KROW;
    float* Qs = Vs + 196 * KROW;
    float* Ps = Qs + 8 * KROW;

    int bh = blockIdx.x;
    int b = bh / NHEAD, h = bh - b * NHEAD;
    int tid = threadIdx.x;
    const float* base = qkv + (size_t)b * NPATCH * QKVN + h * HDIM;

    for (int i = tid; i < NPATCH * 16; i += 256) {
        int row = i >> 4, c4 = (i & 15) * 4;
        *(float4*)(&Ks[row * KROW + c4]) =
            *(const float4*)(base + (size_t)row * QKVN + DMODEL + c4);
        *(float4*)(&Vs[row * KROW + c4]) =
            *(const float4*)(base + (size_t)row * QKVN + 2 * DMODEL + c4);
    }
    __syncthreads();

    int w = tid >> 5, lane = tid & 31;
    const float scale = 0.125f;

    for (int q = w; q < NPATCH; q += 8) {
        for (int d = lane; d < HDIM; d += 32)
            Qs[w * KROW + d] = base[(size_t)q * QKVN + d];
        __syncwarp();

        float sc[7];
        float mx = -1e30f;
#pragma unroll
        for (int kk = 0; kk < 7; kk++) {
            int kidx = lane + kk * 32;
            float s = -1e30f;
            if (kidx < NPATCH) {
                const float4* kr = (const float4*)(&Ks[kidx * KROW]);
                const float4* qr = (const float4*)(&Qs[w * KROW]);
                float a = 0.f;
#pragma unroll
                for (int d4 = 0; d4 < 16; d4++) {
                    float4 kv = kr[d4], qv = qr[d4];
                    a += kv.x * qv.x + kv.y * qv.y + kv.z * qv.z + kv.w * qv.w;
                }
                s = a * scale;
            }
            sc[kk] = s;
            mx = fmaxf(mx, s);
        }
#pragma unroll
        for (int off = 16; off; off >>= 1)
            mx = fmaxf(mx, __shfl_xor_sync(0xffffffffu, mx, off));

        float sum = 0.f;
#pragma unroll
        for (int kk = 0; kk < 7; kk++) {
            int kidx = lane + kk * 32;
            float e = (kidx < NPATCH) ? __expf(sc[kk] - mx) : 0.f;
            sc[kk] = e;
            sum += e;
        }
#pragma unroll
        for (int off = 16; off; off >>= 1)
            sum += __shfl_xor_sync(0xffffffffu, sum, off);
        float inv = 1.f / sum;
#pragma unroll
        for (int kk = 0; kk < 7; kk++) {
            int kidx = lane + kk * 32;
            if (kidx < NPATCH) Ps[w * 200 + kidx] = sc[kk] * inv;
        }
        __syncwarp();

        float o0 = 0.f, o1 = 0.f;
        for (int k = 0; k < NPATCH; k++) {
            float p = Ps[w * 200 + k];
            o0 += p * Vs[k * KROW + lane];
            o1 += p * Vs[k * KROW + lane + 32];
        }
        size_t t = (size_t)b * NPATCH + q;
        o[t * DMODEL + h * HDIM + lane]      = rtf32(o0);   // feeds proj as A
        o[t * DMODEL + h * HDIM + lane + 32] = rtf32(o1);
        __syncwarp();
    }
}

// ---------------- layernorm (rnd: round output to tf32 when feeding a GEMM) ----------------
__global__ void ln_kernel(const float* __restrict__ x, const float* __restrict__ w,
                          const float* __restrict__ bb, float* __restrict__ y, int rnd) {
    int t = blockIdx.x;
    const float* xr = x + (size_t)t * DMODEL;
    int tid = threadIdx.x;
    float v[3];
    float s = 0.f, ss = 0.f;
#pragma unroll
    for (int i = 0; i < 3; i++) {
        v[i] = xr[tid + i * 256];
        s += v[i];
        ss += v[i] * v[i];
    }
    __shared__ float redS[8], redQ[8];
#pragma unroll
    for (int off = 16; off; off >>= 1) {
        s  += __shfl_xor_sync(0xffffffffu, s,  off);
        ss += __shfl_xor_sync(0xffffffffu, ss, off);
    }
    if ((tid & 31) == 0) { redS[tid >> 5] = s; redQ[tid >> 5] = ss; }
    __syncthreads();
    if (tid == 0) {
        float a = 0.f, b2 = 0.f;
#pragma unroll
        for (int i = 0; i < 8; i++) { a += redS[i]; b2 += redQ[i]; }
        float mean = a * (1.0f / DMODEL);
        float var = b2 * (1.0f / DMODEL) - mean * mean;
        redS[0] = mean;
        redQ[0] = rsqrtf(var + 1e-5f);
    }
    __syncthreads();
    float mean = redS[0], rstd = redQ[0];
    float* yr = y + (size_t)t * DMODEL;
#pragma unroll
    for (int i = 0; i < 3; i++) {
        int c = tid + i * 256;
        float o = (v[i] - mean) * rstd * w[c] + bb[c];
        yr[c] = rnd ? rtf32(o) : o;
    }
}

// ---------------- launch ----------------
extern "C" void kernel_launch(void* const* d_in, const int* in_sizes, int n_in,
                              void* d_out, int out_size) {
    const float* x      = (const float*)d_in[0];
    const float* conv_w = (const float*)d_in[1];
    const float* conv_b = (const float*)d_in[2];
    const float* pos    = (const float*)d_in[3];
    const float* ln1w   = (const float*)d_in[4];
    const float* ln1b   = (const float*)d_in[5];
    const float* qkvw   = (const float*)d_in[6];
    const float* qkvb   = (const float*)d_in[7];
    const float* projw  = (const float*)d_in[8];
    const float* projb  = (const float*)d_in[9];
    const float* ln2w   = (const float*)d_in[10];
    const float* ln2b   = (const float*)d_in[11];
    const float* f1w    = (const float*)d_in[12];
    const float* f1b    = (const float*)d_in[13];
    const float* f2w    = (const float*)d_in[14];
    const float* f2b    = (const float*)d_in[15];
    const float* lnfw   = (const float*)d_in[16];
    const float* lnfb   = (const float*)d_in[17];
    float* out = (float*)d_out;

    float *xp, *wpe, *h, *y, *qkv, *o, *act, *rqkvw, *rprojw, *rf1w, *rf2w;
    cudaGetSymbolAddress((void**)&xp,  g_xp);
    cudaGetSymbolAddress((void**)&wpe, g_wpe);
    cudaGetSymbolAddress((void**)&h,   g_h);
    cudaGetSymbolAddress((void**)&y,   g_y);
    cudaGetSymbolAddress((void**)&qkv, g_qkv);
    cudaGetSymbolAddress((void**)&o,   g_o);
    cudaGetSymbolAddress((void**)&act, g_act);
    cudaGetSymbolAddress((void**)&rqkvw,  g_qkvw);
    cudaGetSymbolAddress((void**)&rprojw, g_projw);
    cudaGetSymbolAddress((void**)&rf1w,   g_f1w);
    cudaGetSymbolAddress((void**)&rf2w,   g_f2w);

    cudaFuncSetAttribute(attn_kernel, cudaFuncAttributeMaxDynamicSharedMemorySize, SMEM_ATTN);
    cudaFuncSetAttribute(gemm_tf32<0>, cudaFuncAttributeMaxDynamicSharedMemorySize, GEMM_SMEM);
    cudaFuncSetAttribute(gemm_tf32<1>, cudaFuncAttributeMaxDynamicSharedMemorySize, GEMM_SMEM);
    cudaFuncSetAttribute(gemm_tf32<2>, cudaFuncAttributeMaxDynamicSharedMemorySize, GEMM_SMEM);
    cudaFuncSetAttribute(gemm_tf32<3>, cudaFuncAttributeMaxDynamicSharedMemorySize, GEMM_SMEM);

    // round weights to tf32-RNA once per launch
    {
        int n4;
        n4 = NLAYER * DMODEL * QKVN   / 4; round_kernel<<<(n4 + 255) / 256, 256>>>(qkvw,  rqkvw,  n4);
        n4 = NLAYER * DMODEL * DMODEL / 4; round_kernel<<<(n4 + 255) / 256, 256>>>(projw, rprojw, n4);
        n4 = NLAYER * DMODEL * HIDDEN / 4; round_kernel<<<(n4 + 255) / 256, 256>>>(f1w,   rf1w,   n4);
        n4 = NLAYER * HIDDEN * DMODEL / 4; round_kernel<<<(n4 + 255) / 256, 256>>>(f2w,   rf2w,   n4);
    }

    // patchify + patch-embed GEMM (+bias +pos_embed)
    patch_kernel<<<(TOK * DMODEL + 255) / 256, 256>>>(x, xp);
    transpose_kernel<<<dim3(24, 24), dim3(32, 8)>>>(conv_w, wpe);
    gemm_tf32<3><<<dim3(DMODEL / 128, TOK / 128), 256, GEMM_SMEM>>>(
        xp, wpe, conv_b, pos, h, TOK, DMODEL, DMODEL);

    for (int l = 0; l < NLAYER; l++) {
        ln_kernel<<<TOK, 256>>>(h, ln1w + (size_t)l * DMODEL, ln1b + (size_t)l * DMODEL, y, 1);
        gemm_tf32<0><<<dim3(QKVN / 128, TOK / 128), 256, GEMM_SMEM>>>(
            y, rqkvw + (size_t)l * DMODEL * QKVN, qkvb + (size_t)l * QKVN, nullptr, qkv,
            TOK, QKVN, DMODEL);
        attn_kernel<<<BATCH * NHEAD, 256, SMEM_ATTN>>>(qkv, o);
        gemm_tf32<1><<<dim3(DMODEL / 128, TOK / 128), 256, GEMM_SMEM>>>(
            o, rprojw + (size_t)l * DMODEL * DMODEL, projb + (size_t)l * DMODEL, h, h,
            TOK, DMODEL, DMODEL);
        ln_kernel<<<TOK, 256>>>(h, ln2w + (size_t)l * DMODEL, ln2b + (size_t)l * DMODEL, y, 1);
        gemm_tf32<2><<<dim3(HIDDEN / 128, TOK / 128), 256, GEMM_SMEM>>>(
            y, rf1w + (size_t)l * DMODEL * HIDDEN, f1b + (size_t)l * HIDDEN, nullptr, act,
            TOK, HIDDEN, DMODEL);
        gemm_tf32<1><<<dim3(DMODEL / 128, TOK / 128), 256, GEMM_SMEM>>>(
            act, rf2w + (size_t)l * HIDDEN * DMODEL, f2b + (size_t)l * DMODEL, h, h,
            TOK, DMODEL, HIDDEN);
    }
    ln_kernel<<<TOK, 256>>>(h, lnfw, lnfb, out, 0);
}

// round 8
// speedup vs baseline: 3.0280x; 1.0201x over previous
#include <cuda_runtime.h>
#include <cuda_bf16.h>
#include <math.h>
#include <stdint.h>

// ---------------- problem constants ----------------
#define BATCH   32
#define NPATCH  196
#define TOK     (BATCH * NPATCH)   // 6272
#define DMODEL  768
#define NHEAD   12
#define HDIM    64
#define NLAYER  12
#define HIDDEN  3072
#define QKVN    (3 * DMODEL)       // 2304
#define IMG     224
#define PSZ     16
#define GRID_   14

// ---------------- scratch (no allocations allowed) ----------------
__device__ float g_xp [(size_t)TOK * DMODEL];
__device__ float g_wpe[(size_t)DMODEL * DMODEL];
__device__ float g_h  [(size_t)TOK * DMODEL];
__device__ float g_y  [(size_t)TOK * DMODEL];
__device__ float g_qkv[(size_t)TOK * QKVN];
__device__ float g_o  [(size_t)TOK * DMODEL];
__device__ float g_act[(size_t)TOK * HIDDEN];
// tf32-rounded weights, native [K,N] layout
__device__ float g_qkvw[(size_t)NLAYER * DMODEL * QKVN];
__device__ float g_projw[(size_t)NLAYER * DMODEL * DMODEL];
__device__ float g_f1w [(size_t)NLAYER * DMODEL * HIDDEN];
__device__ float g_f2w [(size_t)NLAYER * HIDDEN * DMODEL];

// ---------------- tf32 round-to-nearest ----------------
__device__ __forceinline__ float rtf32(float x) {
    uint32_t u;
    asm("cvt.rna.tf32.f32 %0, %1;" : "=r"(u) : "f"(x));
    return __uint_as_float(u);
}

// ---------------- weight rounding ----------------
__global__ void round_kernel(const float* __restrict__ src, float* __restrict__ dst, int n4) {
    int i = blockIdx.x * blockDim.x + threadIdx.x;
    if (i >= n4) return;
    float4 v = ((const float4*)src)[i];
    v.x = rtf32(v.x); v.y = rtf32(v.y); v.z = rtf32(v.z); v.w = rtf32(v.w);
    ((float4*)dst)[i] = v;
}

// ---------------- transpose conv_w (D x D) -> wpe[k][d], tf32-rounded ----------------
__global__ void transpose_kernel(const float* __restrict__ src, float* __restrict__ dst) {
    __shared__ float tile[32][33];
    int bx = blockIdx.x * 32;
    int by = blockIdx.y * 32;
    for (int i = threadIdx.y; i < 32; i += 8)
        tile[i][threadIdx.x] = src[(size_t)(by + i) * DMODEL + bx + threadIdx.x];
    __syncthreads();
    for (int i = threadIdx.y; i < 32; i += 8)
        dst[(size_t)(bx + i) * DMODEL + by + threadIdx.x] = rtf32(tile[threadIdx.x][i]);
}

// ---------------- patchify (tf32-rounded) ----------------
__global__ void patch_kernel(const float* __restrict__ x, float* __restrict__ xp) {
    int idx = blockIdx.x * blockDim.x + threadIdx.x;
    if (idx >= TOK * DMODEL) return;
    int t = idx / DMODEL;
    int f = idx - t * DMODEL;
    int b = t / NPATCH;
    int p = t - b * NPATCH;
    int gy = p / GRID_, gx = p - gy * GRID_;
    int c  = f >> 8;
    int py = (f >> 4) & 15;
    int px = f & 15;
    xp[idx] = rtf32(x[(((size_t)b * 3 + c) * IMG + gy * PSZ + py) * IMG + gx * PSZ + px]);
}

// ---------------- TF32 mma.sync GEMM, 64x64 warp tiles ----------------
// C[M,N] = A[M,K] @ B[K,N] + epilogue.
// CTA 128x128, 4 warps (2x2 of 64x64), k-chunk 32, 3-stage cp.async ring.
// OP 0: +bias ; 1: +bias+res[m*N+n] ; 2: +bias,GELU,rtf32 ; 3: +bias+res[(m%196)*N+n]
#define AS_STR 36
#define BS_STR 136
#define STAGE_F (128 * AS_STR + 32 * BS_STR)   // 8960 floats
#define GSTAGES 3
#define GEMM_SMEM (GSTAGES * STAGE_F * 4)      // 107520 bytes

__device__ __forceinline__ void cpasync16(void* dst, const void* src) {
    uint32_t d = (uint32_t)__cvta_generic_to_shared(dst);
    asm volatile("cp.async.cg.shared.global [%0], [%1], 16;" :: "r"(d), "l"(src));
}
__device__ __forceinline__ void mma_tf32(float* c, const uint32_t* a, const uint32_t* b) {
    asm volatile(
        "mma.sync.aligned.m16n8k8.row.col.f32.tf32.tf32.f32 "
        "{%0,%1,%2,%3}, {%4,%5,%6,%7}, {%8,%9}, {%0,%1,%2,%3};"
        : "+f"(c[0]), "+f"(c[1]), "+f"(c[2]), "+f"(c[3])
        : "r"(a[0]), "r"(a[1]), "r"(a[2]), "r"(a[3]), "r"(b[0]), "r"(b[1]));
}

template <int OP>
__global__ void __launch_bounds__(128, 2)
gemm_tf32(const float* __restrict__ A, const float* __restrict__ B,
          const float* __restrict__ bias, const float* __restrict__ res,
          float* __restrict__ C, int M, int N, int K) {
    extern __shared__ float sm[];
    const int tid = threadIdx.x;                  // 128 threads
    const int m0 = blockIdx.y * 128, n0 = blockIdx.x * 128;
    const int warp = tid >> 5, lane = tid & 31;
    const int wm = warp >> 1, wn = warp & 1;      // 2x2 warp grid
    const int g = lane >> 2, tg = lane & 3;

    float acc[4][8][4];
#pragma unroll
    for (int i = 0; i < 4; i++)
#pragma unroll
        for (int j = 0; j < 8; j++)
#pragma unroll
            for (int c = 0; c < 4; c++) acc[i][j][c] = 0.f;

    const int nIter = K >> 5;                     // >= 24 at all call sites

    auto load_stage = [&](int it) {
        float* As = sm + (it % GSTAGES) * STAGE_F;
        float* Bs = As + 128 * AS_STR;
        int k0 = it * 32;
        const float* Ag = A + (size_t)m0 * K + k0;
        const float* Bg = B + (size_t)k0 * N + n0;
#pragma unroll
        for (int i = 0; i < 8; i++) {             // A: 128 rows x 8 chunks of 16B
            int idx = tid + i * 128;
            int r = idx >> 3, c = (idx & 7) * 4;
            cpasync16(&As[r * AS_STR + c], Ag + (size_t)r * K + c);
        }
#pragma unroll
        for (int i = 0; i < 8; i++) {             // B: 32 rows x 32 chunks of 16B
            int idx = tid + i * 128;
            int r = idx >> 5, c = (idx & 31) * 4;
            cpasync16(&Bs[r * BS_STR + c], Bg + (size_t)r * N + c);
        }
        asm volatile("cp.async.commit_group;");
    };

    load_stage(0);
    load_stage(1);

    for (int it = 0; it < nIter; it++) {
        if (it + 2 < nIter) load_stage(it + 2);
        int allow = nIter - 1 - it;
        if (allow >= 2)      asm volatile("cp.async.wait_group 2;");
        else if (allow == 1) asm volatile("cp.async.wait_group 1;");
        else                 asm volatile("cp.async.wait_group 0;");
        __syncthreads();

        const float* As = sm + (it % GSTAGES) * STAGE_F;
        const float* Bs = As + 128 * AS_STR;
#pragma unroll
        for (int kk = 0; kk < 4; kk++) {
            uint32_t a[4][4], b[8][2];
#pragma unroll
            for (int mi = 0; mi < 4; mi++) {
                const float* p = As + (wm * 64 + mi * 16 + g) * AS_STR + kk * 8 + tg;
                a[mi][0] = __float_as_uint(p[0]);
                a[mi][1] = __float_as_uint(p[8 * AS_STR]);
                a[mi][2] = __float_as_uint(p[4]);
                a[mi][3] = __float_as_uint(p[8 * AS_STR + 4]);
            }
#pragma unroll
            for (int ni = 0; ni < 8; ni++) {
                const float* q = Bs + (kk * 8 + tg) * BS_STR + wn * 64 + ni * 8 + g;
                b[ni][0] = __float_as_uint(q[0]);
                b[ni][1] = __float_as_uint(q[4 * BS_STR]);
            }
#pragma unroll
            for (int mi = 0; mi < 4; mi++)
#pragma unroll
                for (int ni = 0; ni < 8; ni++)
                    mma_tf32(acc[mi][ni], a[mi], b[ni]);
        }
        __syncthreads();
    }

    // ---- epilogue: float2 stores ----
#pragma unroll
    for (int mi = 0; mi < 4; mi++) {
        int r0 = m0 + wm * 64 + mi * 16 + g;
#pragma unroll
        for (int ni = 0; ni < 8; ni++) {
            int n = n0 + wn * 64 + ni * 8 + tg * 2;
            float2 bi = *(const float2*)(bias + n);
#pragma unroll
            for (int half = 0; half < 2; half++) {
                int m = r0 + half * 8;
                float v0 = acc[mi][ni][half * 2 + 0] + bi.x;
                float v1 = acc[mi][ni][half * 2 + 1] + bi.y;
                if (OP == 1) {
                    float2 rv = *(const float2*)(res + (size_t)m * N + n);
                    v0 += rv.x; v1 += rv.y;
                }
                if (OP == 2) {
                    v0 = rtf32(0.5f * v0 * (1.0f + erff(v0 * 0.70710678118654752f)));
                    v1 = rtf32(0.5f * v1 * (1.0f + erff(v1 * 0.70710678118654752f)));
                }
                if (OP == 3) {
                    float2 rv = *(const float2*)(res + (size_t)(m % NPATCH) * N + n);
                    v0 += rv.x; v1 += rv.y;
                }
                *(float2*)(C + (size_t)m * N + n) = make_float2(v0, v1);
            }
        }
    }
}

// ---------------- attention: per (b, head) block (fp32) ----------------
#define KROW 68
#define SMEM_ATTN ((2 * 196 * KROW + 8 * KROW + 8 * 200) * 4)

__global__ void attn_kernel(const float* __restrict__ qkv, float* __restrict__ o) {
    extern __shared__ float smA[];
    float* Ks = smA;
    float* Vs = Ks + 196 * KROW;
    float* Qs = Vs + 196 * KROW;
    float* Ps = Qs + 8 * KROW;

    int bh = blockIdx.x;
    int b = bh / NHEAD, h = bh - b * NHEAD;
    int tid = threadIdx.x;
    const float* base = qkv + (size_t)b * NPATCH * QKVN + h * HDIM;

    for (int i = tid; i < NPATCH * 16; i += 256) {
        int row = i >> 4, c4 = (i & 15) * 4;
        *(float4*)(&Ks[row * KROW + c4]) =
            *(const float4*)(base + (size_t)row * QKVN + DMODEL + c4);
        *(float4*)(&Vs[row * KROW + c4]) =
            *(const float4*)(base + (size_t)row * QKVN + 2 * DMODEL + c4);
    }
    __syncthreads();

    int w = tid >> 5, lane = tid & 31;
    const float scale = 0.125f;

    for (int q = w; q < NPATCH; q += 8) {
        for (int d = lane; d < HDIM; d += 32)
            Qs[w * KROW + d] = base[(size_t)q * QKVN + d];
        __syncwarp();

        float sc[7];
        float mx = -1e30f;
#pragma unroll
        for (int kk = 0; kk < 7; kk++) {
            int kidx = lane + kk * 32;
            float s = -1e30f;
            if (kidx < NPATCH) {
                const float4* kr = (const float4*)(&Ks[kidx * KROW]);
                const float4* qr = (const float4*)(&Qs[w * KROW]);
                float a = 0.f;
#pragma unroll
                for (int d4 = 0; d4 < 16; d4++) {
                    float4 kv = kr[d4], qv = qr[d4];
                    a += kv.x * qv.x + kv.y * qv.y + kv.z * qv.z + kv.w * qv.w;
                }
                s = a * scale;
            }
            sc[kk] = s;
            mx = fmaxf(mx, s);
        }
#pragma unroll
        for (int off = 16; off; off >>= 1)
            mx = fmaxf(mx, __shfl_xor_sync(0xffffffffu, mx, off));

        float sum = 0.f;
#pragma unroll
        for (int kk = 0; kk < 7; kk++) {
            int kidx = lane + kk * 32;
            float e = (kidx < NPATCH) ? __expf(sc[kk] - mx) : 0.f;
            sc[kk] = e;
            sum += e;
        }
#pragma unroll
        for (int off = 16; off; off >>= 1)
            sum += __shfl_xor_sync(0xffffffffu, sum, off);
        float inv = 1.f / sum;
#pragma unroll
        for (int kk = 0; kk < 7; kk++) {
            int kidx = lane + kk * 32;
            if (kidx < NPATCH) Ps[w * 200 + kidx] = sc[kk] * inv;
        }
        __syncwarp();

        float o0 = 0.f, o1 = 0.f;
        for (int k = 0; k < NPATCH; k++) {
            float p = Ps[w * 200 + k];
            o0 += p * Vs[k * KROW + lane];
            o1 += p * Vs[k * KROW + lane + 32];
        }
        size_t t = (size_t)b * NPATCH + q;
        o[t * DMODEL + h * HDIM + lane]      = rtf32(o0);
        o[t * DMODEL + h * HDIM + lane + 32] = rtf32(o1);
        __syncwarp();
    }
}

// ---------------- layernorm ----------------
__global__ void ln_kernel(const float* __restrict__ x, const float* __restrict__ w,
                          const float* __restrict__ bb, float* __restrict__ y, int rnd) {
    int t = blockIdx.x;
    const float* xr = x + (size_t)t * DMODEL;
    int tid = threadIdx.x;
    float v[3];
    float s = 0.f, ss = 0.f;
#pragma unroll
    for (int i = 0; i < 3; i++) {
        v[i] = xr[tid + i * 256];
        s += v[i];
        ss += v[i] * v[i];
    }
    __shared__ float redS[8], redQ[8];
#pragma unroll
    for (int off = 16; off; off >>= 1) {
        s  += __shfl_xor_sync(0xffffffffu, s,  off);
        ss += __shfl_xor_sync(0xffffffffu, ss, off);
    }
    if ((tid & 31) == 0) { redS[tid >> 5] = s; redQ[tid >> 5] = ss; }
    __syncthreads();
    if (tid == 0) {
        float a = 0.f, b2 = 0.f;
#pragma unroll
        for (int i = 0; i < 8; i++) { a += redS[i]; b2 += redQ[i]; }
        float mean = a * (1.0f / DMODEL);
        float var = b2 * (1.0f / DMODEL) - mean * mean;
        redS[0] = mean;
        redQ[0] = rsqrtf(var + 1e-5f);
    }
    __syncthreads();
    float mean = redS[0], rstd = redQ[0];
    float* yr = y + (size_t)t * DMODEL;
#pragma unroll
    for (int i = 0; i < 3; i++) {
        int c = tid + i * 256;
        float o = (v[i] - mean) * rstd * w[c] + bb[c];
        yr[c] = rnd ? rtf32(o) : o;
    }
}

// ---------------- launch ----------------
extern "C" void kernel_launch(void* const* d_in, const int* in_sizes, int n_in,
                              void* d_out, int out_size) {
    const float* x      = (const float*)d_in[0];
    const float* conv_w = (const float*)d_in[1];
    const float* conv_b = (const float*)d_in[2];
    const float* pos    = (const float*)d_in[3];
    const float* ln1w   = (const float*)d_in[4];
    const float* ln1b   = (const float*)d_in[5];
    const float* qkvw   = (const float*)d_in[6];
    const float* qkvb   = (const float*)d_in[7];
    const float* projw  = (const float*)d_in[8];
    const float* projb  = (const float*)d_in[9];
    const float* ln2w   = (const float*)d_in[10];
    const float* ln2b   = (const float*)d_in[11];
    const float* f1w    = (const float*)d_in[12];
    const float* f1b    = (const float*)d_in[13];
    const float* f2w    = (const float*)d_in[14];
    const float* f2b    = (const float*)d_in[15];
    const float* lnfw   = (const float*)d_in[16];
    const float* lnfb   = (const float*)d_in[17];
    float* out = (float*)d_out;

    float *xp, *wpe, *h, *y, *qkv, *o, *act, *rqkvw, *rprojw, *rf1w, *rf2w;
    cudaGetSymbolAddress((void**)&xp,  g_xp);
    cudaGetSymbolAddress((void**)&wpe, g_wpe);
    cudaGetSymbolAddress((void**)&h,   g_h);
    cudaGetSymbolAddress((void**)&y,   g_y);
    cudaGetSymbolAddress((void**)&qkv, g_qkv);
    cudaGetSymbolAddress((void**)&o,   g_o);
    cudaGetSymbolAddress((void**)&act, g_act);
    cudaGetSymbolAddress((void**)&rqkvw,  g_qkvw);
    cudaGetSymbolAddress((void**)&rprojw, g_projw);
    cudaGetSymbolAddress((void**)&rf1w,   g_f1w);
    cudaGetSymbolAddress((void**)&rf2w,   g_f2w);

    cudaFuncSetAttribute(attn_kernel, cudaFuncAttributeMaxDynamicSharedMemorySize, SMEM_ATTN);
    cudaFuncSetAttribute(gemm_tf32<0>, cudaFuncAttributeMaxDynamicSharedMemorySize, GEMM_SMEM);
    cudaFuncSetAttribute(gemm_tf32<1>, cudaFuncAttributeMaxDynamicSharedMemorySize, GEMM_SMEM);
    cudaFuncSetAttribute(gemm_tf32<2>, cudaFuncAttributeMaxDynamicSharedMemorySize, GEMM_SMEM);
    cudaFuncSetAttribute(gemm_tf32<3>, cudaFuncAttributeMaxDynamicSharedMemorySize, GEMM_SMEM);

    // round weights to tf32-RNA once per launch (native [K,N] layout)
    {
        int n4;
        n4 = NLAYER * DMODEL * QKVN   / 4; round_kernel<<<(n4 + 255) / 256, 256>>>(qkvw,  rqkvw,  n4);
        n4 = NLAYER * DMODEL * DMODEL / 4; round_kernel<<<(n4 + 255) / 256, 256>>>(projw, rprojw, n4);
        n4 = NLAYER * DMODEL * HIDDEN / 4; round_kernel<<<(n4 + 255) / 256, 256>>>(f1w,   rf1w,   n4);
        n4 = NLAYER * HIDDEN * DMODEL / 4; round_kernel<<<(n4 + 255) / 256, 256>>>(f2w,   rf2w,   n4);
    }

    // patchify + patch-embed GEMM (+bias +pos_embed)
    patch_kernel<<<(TOK * DMODEL + 255) / 256, 256>>>(x, xp);
    transpose_kernel<<<dim3(24, 24), dim3(32, 8)>>>(conv_w, wpe);
    gemm_tf32<3><<<dim3(DMODEL / 128, TOK / 128), 128, GEMM_SMEM>>>(
        xp, wpe, conv_b, pos, h, TOK, DMODEL, DMODEL);

    for (int l = 0; l < NLAYER; l++) {
        ln_kernel<<<TOK, 256>>>(h, ln1w + (size_t)l * DMODEL, ln1b + (size_t)l * DMODEL, y, 1);
        gemm_tf32<0><<<dim3(QKVN / 128, TOK / 128), 128, GEMM_SMEM>>>(
            y, rqkvw + (size_t)l * DMODEL * QKVN, qkvb + (size_t)l * QKVN, nullptr, qkv,
            TOK, QKVN, DMODEL);
        attn_kernel<<<BATCH * NHEAD, 256, SMEM_ATTN>>>(qkv, o);
        gemm_tf32<1><<<dim3(DMODEL / 128, TOK / 128), 128, GEMM_SMEM>>>(
            o, rprojw + (size_t)l * DMODEL * DMODEL, projb + (size_t)l * DMODEL, h, h,
            TOK, DMODEL, DMODEL);
        ln_kernel<<<TOK, 256>>>(h, ln2w + (size_t)l * DMODEL, ln2b + (size_t)l * DMODEL, y, 1);
        gemm_tf32<2><<<dim3(HIDDEN / 128, TOK / 128), 128, GEMM_SMEM>>>(
            y, rf1w + (size_t)l * DMODEL * HIDDEN, f1b + (size_t)l * HIDDEN, nullptr, act,
            TOK, HIDDEN, DMODEL);
        gemm_tf32<1><<<dim3(DMODEL / 128, TOK / 128), 128, GEMM_SMEM>>>(
            act, rf2w + (size_t)l * HIDDEN * DMODEL, f2b + (size_t)l * DMODEL, h, h,
            TOK, DMODEL, HIDDEN);
    }
    ln_kernel<<<TOK, 256>>>(h, lnfw, lnfb, out, 0);
}

// round 9
// speedup vs baseline: 4.1965x; 1.3859x over previous
#include <cuda_runtime.h>
#include <cuda_fp16.h>
#include <math.h>
#include <stdint.h>

// ---------------- problem constants ----------------
#define BATCH   32
#define NPATCH  196
#define TOK     (BATCH * NPATCH)   // 6272
#define DMODEL  768
#define NHEAD   12
#define HDIM    64
#define NLAYER  12
#define HIDDEN  3072
#define QKVN    (3 * DMODEL)       // 2304
#define IMG     224
#define PSZ     16
#define GRID_   14

// ---------------- scratch (no allocations allowed) ----------------
__device__ float  g_h  [(size_t)TOK * DMODEL];     // residual stream (fp32)
__device__ float  g_qkv[(size_t)TOK * QKVN];       // qkv (fp32, softmax precision)
__device__ __half h_xp [(size_t)TOK * DMODEL];     // patchified input (half)
__device__ __half h_y  [(size_t)TOK * DMODEL];     // LN output (half)
__device__ __half h_o  [(size_t)TOK * DMODEL];     // attention output (half)
__device__ __half h_act[(size_t)TOK * HIDDEN];     // GELU output (half)
// half weights, [N,K] K-major
__device__ __half w_pe  [(size_t)DMODEL * DMODEL];
__device__ __half w_qkv [(size_t)NLAYER * DMODEL * QKVN];
__device__ __half w_proj[(size_t)NLAYER * DMODEL * DMODEL];
__device__ __half w_f1  [(size_t)NLAYER * DMODEL * HIDDEN];
__device__ __half w_f2  [(size_t)NLAYER * HIDDEN * DMODEL];

// ---------------- helpers ----------------
__device__ __forceinline__ uint32_t smem_u32(const void* p) {
    uint32_t a;
    asm("{ .reg .u64 t; cvta.to.shared.u64 t, %1; cvt.u32.u64 %0, t; }" : "=r"(a) : "l"(p));
    return a;
}
__device__ __forceinline__ void cpasync16(void* dst, const void* src) {
    uint32_t d = (uint32_t)__cvta_generic_to_shared(dst);
    asm volatile("cp.async.cg.shared.global [%0], [%1], 16;" :: "r"(d), "l"(src));
}
__device__ __forceinline__ void ldmx4(uint32_t* r, uint32_t addr) {
    asm volatile("ldmatrix.sync.aligned.m8n8.x4.shared.b16 {%0,%1,%2,%3}, [%4];"
                 : "=r"(r[0]), "=r"(r[1]), "=r"(r[2]), "=r"(r[3]) : "r"(addr));
}
__device__ __forceinline__ void mma_f16(float* c, const uint32_t* a,
                                        uint32_t b0, uint32_t b1) {
    asm volatile(
        "mma.sync.aligned.m16n8k16.row.col.f32.f16.f16.f32 "
        "{%0,%1,%2,%3}, {%4,%5,%6,%7}, {%8,%9}, {%0,%1,%2,%3};"
        : "+f"(c[0]), "+f"(c[1]), "+f"(c[2]), "+f"(c[3])
        : "r"(a[0]), "r"(a[1]), "r"(a[2]), "r"(a[3]), "r"(b0), "r"(b1));
}

// ---------------- weight conversion ----------------
// transpose+convert: src fp32 [K,N] (per layer) -> dst half [N,K]
__global__ void tr_half_kernel(const float* __restrict__ src, __half* __restrict__ dst,
                               int K, int N) {
    __shared__ float t[32][33];
    size_t off = (size_t)blockIdx.z * K * N;
    src += off; dst += off;
    int kb = blockIdx.y * 32, nb = blockIdx.x * 32;
    for (int i = threadIdx.y; i < 32; i += 8)
        t[i][threadIdx.x] = src[(size_t)(kb + i) * N + nb + threadIdx.x];
    __syncthreads();
    for (int i = threadIdx.y; i < 32; i += 8)
        dst[(size_t)(nb + i) * K + kb + threadIdx.x] = __float2half_rn(t[threadIdx.x][i]);
}
// elementwise convert (conv_w is already [N,K])
__global__ void cvt_half_kernel(const float* __restrict__ src, __half* __restrict__ dst, int n) {
    int i = blockIdx.x * blockDim.x + threadIdx.x;
    if (i < n) dst[i] = __float2half_rn(src[i]);
}

// ---------------- patchify -> half ----------------
__global__ void patch_kernel(const float* __restrict__ x, __half* __restrict__ xp) {
    int idx = blockIdx.x * blockDim.x + threadIdx.x;
    if (idx >= TOK * DMODEL) return;
    int t = idx / DMODEL;
    int f = idx - t * DMODEL;
    int b = t / NPATCH;
    int p = t - b * NPATCH;
    int gy = p / GRID_, gx = p - gy * GRID_;
    int c  = f >> 8;
    int py = (f >> 4) & 15;
    int px = f & 15;
    xp[idx] = __float2half_rn(
        x[(((size_t)b * 3 + c) * IMG + gy * PSZ + py) * IMG + gx * PSZ + px]);
}

// ---------------- FP16 mma.sync GEMM ----------------
// C[M,N] = A[M,K] @ B[N,K]^T, A/B half, accum fp32.
// CTA 128x128, 4 warps (2x2 of 64x64), k-chunk 32, 3-stage cp.async ring, ldmatrix frags.
// OP 0: +bias -> fp32 ; 1: +bias+res -> fp32 ; 2: +bias,GELU -> HALF ; 3: +bias+pos -> fp32
#define ASTR 40                                  // halfs per row (80B): conflict-free perm
#define AB_HALFS (128 * ASTR)                    // 5120 halfs per operand
#define STAGE_BYTES (2 * AB_HALFS * 2)           // 20480
#define GSTAGES 3
#define GEMM_SMEM (GSTAGES * STAGE_BYTES)        // 61440

template <int OP>
__global__ void __launch_bounds__(128, 2)
gemm_fp16(const __half* __restrict__ A, const __half* __restrict__ B,
          const float* __restrict__ bias, const float* __restrict__ res,
          void* __restrict__ Cout, int M, int N, int K) {
    extern __shared__ __half sm[];
    const int tid = threadIdx.x;                  // 128 threads
    const int m0 = blockIdx.y * 128, n0 = blockIdx.x * 128;
    const int warp = tid >> 5, lane = tid & 31;
    const int wm = warp >> 1, wn = warp & 1;      // 2x2 warp grid
    const int g = lane >> 2, tg = lane & 3;

    const uint32_t smb = smem_u32(sm);
    uint32_t aAddr[4], bAddr[4];
#pragma unroll
    for (int mi = 0; mi < 4; mi++)
        aAddr[mi] = smb + ((wm * 64 + mi * 16 + (lane & 15)) * ASTR +
                           ((lane >> 4) & 1) * 8) * 2;
#pragma unroll
    for (int n2 = 0; n2 < 4; n2++)
        bAddr[n2] = smb + AB_HALFS * 2 +
                    ((wn * 64 + n2 * 16 + (lane & 7) + ((lane >> 4) & 1) * 8) * ASTR +
                     ((lane >> 3) & 1) * 8) * 2;

    float acc[4][8][4];
#pragma unroll
    for (int i = 0; i < 4; i++)
#pragma unroll
        for (int j = 0; j < 8; j++)
#pragma unroll
            for (int c = 0; c < 4; c++) acc[i][j][c] = 0.f;

    const int nIter = K >> 5;

    auto load_stage = [&](int it) {
        __half* As = sm + (it % GSTAGES) * (STAGE_BYTES / 2);
        __half* Bs = As + AB_HALFS;
        int k0 = it * 32;
        const __half* Ag = A + (size_t)m0 * K + k0;
        const __half* Bg = B + (size_t)n0 * K + k0;
#pragma unroll
        for (int i = 0; i < 4; i++) {             // 128 rows x 4 chunks of 8 halfs
            int idx = tid + i * 128;
            int r = idx >> 2, c = (idx & 3) * 8;
            cpasync16(&As[r * ASTR + c], Ag + (size_t)r * K + c);
        }
#pragma unroll
        for (int i = 0; i < 4; i++) {
            int idx = tid + i * 128;
            int r = idx >> 2, c = (idx & 3) * 8;
            cpasync16(&Bs[r * ASTR + c], Bg + (size_t)r * K + c);
        }
        asm volatile("cp.async.commit_group;");
    };

    load_stage(0);
    load_stage(1);

    for (int it = 0; it < nIter; it++) {
        if (it + 2 < nIter) load_stage(it + 2);
        int allow = nIter - 1 - it;
        if (allow >= 2)      asm volatile("cp.async.wait_group 2;");
        else if (allow == 1) asm volatile("cp.async.wait_group 1;");
        else                 asm volatile("cp.async.wait_group 0;");
        __syncthreads();

        uint32_t stOff = (uint32_t)((it % GSTAGES) * STAGE_BYTES);
#pragma unroll
        for (int kk = 0; kk < 2; kk++) {          // two k=16 steps per 32-chunk
            uint32_t a[4][4], b[4][4];
#pragma unroll
            for (int mi = 0; mi < 4; mi++) ldmx4(a[mi], aAddr[mi] + stOff + kk * 32);
#pragma unroll
            for (int n2 = 0; n2 < 4; n2++) ldmx4(b[n2], bAddr[n2] + stOff + kk * 32);
#pragma unroll
            for (int mi = 0; mi < 4; mi++)
#pragma unroll
                for (int n2 = 0; n2 < 4; n2++) {
                    mma_f16(acc[mi][n2 * 2 + 0], a[mi], b[n2][0], b[n2][1]);
                    mma_f16(acc[mi][n2 * 2 + 1], a[mi], b[n2][2], b[n2][3]);
                }
        }
        __syncthreads();
    }

    // ---- epilogue ----
    float* Cf = (float*)Cout;
    __half* Ch = (__half*)Cout;
#pragma unroll
    for (int mi = 0; mi < 4; mi++) {
        int r0 = m0 + wm * 64 + mi * 16 + g;
#pragma unroll
        for (int ni = 0; ni < 8; ni++) {
            int n = n0 + wn * 64 + ni * 8 + tg * 2;
            float2 bi = *(const float2*)(bias + n);
#pragma unroll
            for (int half = 0; half < 2; half++) {
                int m = r0 + half * 8;
                float v0 = acc[mi][ni][half * 2 + 0] + bi.x;
                float v1 = acc[mi][ni][half * 2 + 1] + bi.y;
                if (OP == 1) {
                    float2 rv = *(const float2*)(res + (size_t)m * N + n);
                    v0 += rv.x; v1 += rv.y;
                }
                if (OP == 3) {
                    float2 rv = *(const float2*)(res + (size_t)(m % NPATCH) * N + n);
                    v0 += rv.x; v1 += rv.y;
                }
                if (OP == 2) {
                    v0 = 0.5f * v0 * (1.0f + erff(v0 * 0.70710678118654752f));
                    v1 = 0.5f * v1 * (1.0f + erff(v1 * 0.70710678118654752f));
                    *(__half2*)(Ch + (size_t)m * N + n) = __floats2half2_rn(v0, v1);
                } else {
                    *(float2*)(Cf + (size_t)m * N + n) = make_float2(v0, v1);
                }
            }
        }
    }
}

// ---------------- attention: per (b, head) block (fp32 compute, half out) ----------------
#define KROW 68
#define SMEM_ATTN ((2 * 196 * KROW + 8 * KROW + 8 * 200) * 4)

__global__ void attn_kernel(const float* __restrict__ qkv, __half* __restrict__ o) {
    extern __shared__ float smA[];
    float* Ks = smA;
    float* Vs = Ks + 196 * KROW;
    float* Qs = Vs + 196 * KROW;
    float* Ps = Qs + 8 * KROW;

    int bh = blockIdx.x;
    int b = bh / NHEAD, h = bh - b * NHEAD;
    int tid = threadIdx.x;
    const float* base = qkv + (size_t)b * NPATCH * QKVN + h * HDIM;

    for (int i = tid; i < NPATCH * 16; i += 256) {
        int row = i >> 4, c4 = (i & 15) * 4;
        *(float4*)(&Ks[row * KROW + c4]) =
            *(const float4*)(base + (size_t)row * QKVN + DMODEL + c4);
        *(float4*)(&Vs[row * KROW + c4]) =
            *(const float4*)(base + (size_t)row * QKVN + 2 * DMODEL + c4);
    }
    __syncthreads();

    int w = tid >> 5, lane = tid & 31;
    const float scale = 0.125f;

    for (int q = w; q < NPATCH; q += 8) {
        for (int d = lane; d < HDIM; d += 32)
            Qs[w * KROW + d] = base[(size_t)q * QKVN + d];
        __syncwarp();

        float sc[7];
        float mx = -1e30f;
#pragma unroll
        for (int kk = 0; kk < 7; kk++) {
            int kidx = lane + kk * 32;
            float s = -1e30f;
            if (kidx < NPATCH) {
                const float4* kr = (const float4*)(&Ks[kidx * KROW]);
                const float4* qr = (const float4*)(&Qs[w * KROW]);
                float a = 0.f;
#pragma unroll
                for (int d4 = 0; d4 < 16; d4++) {
                    float4 kv = kr[d4], qv = qr[d4];
                    a += kv.x * qv.x + kv.y * qv.y + kv.z * qv.z + kv.w * qv.w;
                }
                s = a * scale;
            }
            sc[kk] = s;
            mx = fmaxf(mx, s);
        }
#pragma unroll
        for (int off = 16; off; off >>= 1)
            mx = fmaxf(mx, __shfl_xor_sync(0xffffffffu, mx, off));

        float sum = 0.f;
#pragma unroll
        for (int kk = 0; kk < 7; kk++) {
            int kidx = lane + kk * 32;
            float e = (kidx < NPATCH) ? __expf(sc[kk] - mx) : 0.f;
            sc[kk] = e;
            sum += e;
        }
#pragma unroll
        for (int off = 16; off; off >>= 1)
            sum += __shfl_xor_sync(0xffffffffu, sum, off);
        float inv = 1.f / sum;
#pragma unroll
        for (int kk = 0; kk < 7; kk++) {
            int kidx = lane + kk * 32;
            if (kidx < NPATCH) Ps[w * 200 + kidx] = sc[kk] * inv;
        }
        __syncwarp();

        float o0 = 0.f, o1 = 0.f;
        for (int k = 0; k < NPATCH; k++) {
            float p = Ps[w * 200 + k];
            o0 += p * Vs[k * KROW + lane];
            o1 += p * Vs[k * KROW + lane + 32];
        }
        size_t t = (size_t)b * NPATCH + q;
        o[t * DMODEL + h * HDIM + lane]      = __float2half_rn(o0);
        o[t * DMODEL + h * HDIM + lane + 32] = __float2half_rn(o1);
        __syncwarp();
    }
}

// ---------------- layernorm (templated output type) ----------------
template <typename TOUT>
__global__ void ln_kernel(const float* __restrict__ x, const float* __restrict__ w,
                          const float* __restrict__ bb, TOUT* __restrict__ y) {
    int t = blockIdx.x;
    const float* xr = x + (size_t)t * DMODEL;
    int tid = threadIdx.x;
    float v[3];
    float s = 0.f, ss = 0.f;
#pragma unroll
    for (int i = 0; i < 3; i++) {
        v[i] = xr[tid + i * 256];
        s += v[i];
        ss += v[i] * v[i];
    }
    __shared__ float redS[8], redQ[8];
#pragma unroll
    for (int off = 16; off; off >>= 1) {
        s  += __shfl_xor_sync(0xffffffffu, s,  off);
        ss += __shfl_xor_sync(0xffffffffu, ss, off);
    }
    if ((tid & 31) == 0) { redS[tid >> 5] = s; redQ[tid >> 5] = ss; }
    __syncthreads();
    if (tid == 0) {
        float a = 0.f, b2 = 0.f;
#pragma unroll
        for (int i = 0; i < 8; i++) { a += redS[i]; b2 += redQ[i]; }
        float mean = a * (1.0f / DMODEL);
        float var = b2 * (1.0f / DMODEL) - mean * mean;
        redS[0] = mean;
        redQ[0] = rsqrtf(var + 1e-5f);
    }
    __syncthreads();
    float mean = redS[0], rstd = redQ[0];
    TOUT* yr = y + (size_t)t * DMODEL;
#pragma unroll
    for (int i = 0; i < 3; i++) {
        int c = tid + i * 256;
        float o = (v[i] - mean) * rstd * w[c] + bb[c];
        yr[c] = (TOUT)o;
    }
}

// ---------------- launch ----------------
extern "C" void kernel_launch(void* const* d_in, const int* in_sizes, int n_in,
                              void* d_out, int out_size) {
    const float* x      = (const float*)d_in[0];
    const float* conv_w = (const float*)d_in[1];
    const float* conv_b = (const float*)d_in[2];
    const float* pos    = (const float*)d_in[3];
    const float* ln1w   = (const float*)d_in[4];
    const float* ln1b   = (const float*)d_in[5];
    const float* qkvw   = (const float*)d_in[6];
    const float* qkvb   = (const float*)d_in[7];
    const float* projw  = (const float*)d_in[8];
    const float* projb  = (const float*)d_in[9];
    const float* ln2w   = (const float*)d_in[10];
    const float* ln2b   = (const float*)d_in[11];
    const float* f1w    = (const float*)d_in[12];
    const float* f1b    = (const float*)d_in[13];
    const float* f2w    = (const float*)d_in[14];
    const float* f2b    = (const float*)d_in[15];
    const float* lnfw   = (const float*)d_in[16];
    const float* lnfb   = (const float*)d_in[17];
    float* out = (float*)d_out;

    float *h, *qkv;
    __half *xp, *y, *o, *act, *wpe, *rqkvw, *rprojw, *rf1w, *rf2w;
    cudaGetSymbolAddress((void**)&h,   g_h);
    cudaGetSymbolAddress((void**)&qkv, g_qkv);
    cudaGetSymbolAddress((void**)&xp,  h_xp);
    cudaGetSymbolAddress((void**)&y,   h_y);
    cudaGetSymbolAddress((void**)&o,   h_o);
    cudaGetSymbolAddress((void**)&act, h_act);
    cudaGetSymbolAddress((void**)&wpe, w_pe);
    cudaGetSymbolAddress((void**)&rqkvw,  w_qkv);
    cudaGetSymbolAddress((void**)&rprojw, w_proj);
    cudaGetSymbolAddress((void**)&rf1w,   w_f1);
    cudaGetSymbolAddress((void**)&rf2w,   w_f2);

    cudaFuncSetAttribute(attn_kernel, cudaFuncAttributeMaxDynamicSharedMemorySize, SMEM_ATTN);
    cudaFuncSetAttribute(gemm_fp16<0>, cudaFuncAttributeMaxDynamicSharedMemorySize, GEMM_SMEM);
    cudaFuncSetAttribute(gemm_fp16<1>, cudaFuncAttributeMaxDynamicSharedMemorySize, GEMM_SMEM);
    cudaFuncSetAttribute(gemm_fp16<2>, cudaFuncAttributeMaxDynamicSharedMemorySize, GEMM_SMEM);
    cudaFuncSetAttribute(gemm_fp16<3>, cudaFuncAttributeMaxDynamicSharedMemorySize, GEMM_SMEM);

    // weights -> half, [N,K] (transpose), once per launch; conv_w is already [N,K]
    {
        dim3 blk(32, 8);
        tr_half_kernel<<<dim3(QKVN  / 32, DMODEL / 32, NLAYER), blk>>>(qkvw,  rqkvw,  DMODEL, QKVN);
        tr_half_kernel<<<dim3(DMODEL/ 32, DMODEL / 32, NLAYER), blk>>>(projw, rprojw, DMODEL, DMODEL);
        tr_half_kernel<<<dim3(HIDDEN/ 32, DMODEL / 32, NLAYER), blk>>>(f1w,   rf1w,   DMODEL, HIDDEN);
        tr_half_kernel<<<dim3(DMODEL/ 32, HIDDEN / 32, NLAYER), blk>>>(f2w,   rf2w,   HIDDEN, DMODEL);
        int n = DMODEL * DMODEL;
        cvt_half_kernel<<<(n + 255) / 256, 256>>>(conv_w, wpe, n);
    }

    // patchify + patch-embed GEMM (+bias +pos_embed)
    patch_kernel<<<(TOK * DMODEL + 255) / 256, 256>>>(x, xp);
    gemm_fp16<3><<<dim3(DMODEL / 128, TOK / 128), 128, GEMM_SMEM>>>(
        xp, wpe, conv_b, pos, h, TOK, DMODEL, DMODEL);

    for (int l = 0; l < NLAYER; l++) {
        ln_kernel<__half><<<TOK, 256>>>(h, ln1w + (size_t)l * DMODEL, ln1b + (size_t)l * DMODEL, y);
        gemm_fp16<0><<<dim3(QKVN / 128, TOK / 128), 128, GEMM_SMEM>>>(
            y, rqkvw + (size_t)l * DMODEL * QKVN, qkvb + (size_t)l * QKVN, nullptr, qkv,
            TOK, QKVN, DMODEL);
        attn_kernel<<<BATCH * NHEAD, 256, SMEM_ATTN>>>(qkv, o);
        gemm_fp16<1><<<dim3(DMODEL / 128, TOK / 128), 128, GEMM_SMEM>>>(
            o, rprojw + (size_t)l * DMODEL * DMODEL, projb + (size_t)l * DMODEL, h, h,
            TOK, DMODEL, DMODEL);
        ln_kernel<__half><<<TOK, 256>>>(h, ln2w + (size_t)l * DMODEL, ln2b + (size_t)l * DMODEL, y);
        gemm_fp16<2><<<dim3(HIDDEN / 128, TOK / 128), 128, GEMM_SMEM>>>(
            y, rf1w + (size_t)l * DMODEL * HIDDEN, f1b + (size_t)l * HIDDEN, nullptr, act,
            TOK, HIDDEN, DMODEL);
        gemm_fp16<1><<<dim3(DMODEL / 128, TOK / 128), 128, GEMM_SMEM>>>(
            act, rf2w + (size_t)l * HIDDEN * DMODEL, f2b + (size_t)l * DMODEL, h, h,
            TOK, DMODEL, HIDDEN);
    }
    ln_kernel<float><<<TOK, 256>>>(h, lnfw, lnfb, out);
}

// round 11
// speedup vs baseline: 4.3107x; 1.0272x over previous
#include <cuda_runtime.h>
#include <cuda_fp16.h>
#include <math.h>
#include <stdint.h>

// ---------------- problem constants ----------------
#define BATCH   32
#define NPATCH  196
#define TOK     (BATCH * NPATCH)   // 6272
#define DMODEL  768
#define NHEAD   12
#define HDIM    64
#define NLAYER  12
#define HIDDEN  3072
#define QKVN    (3 * DMODEL)       // 2304
#define IMG     224
#define PSZ     16
#define GRID_   14

// ---------------- scratch (no allocations allowed) ----------------
__device__ float  g_h  [(size_t)TOK * DMODEL];     // residual stream (fp32)
__device__ float  g_qkv[(size_t)TOK * QKVN];       // qkv (fp32, softmax precision)
__device__ __half h_xp [(size_t)TOK * DMODEL];     // patchified input (half)
__device__ __half h_y  [(size_t)TOK * DMODEL];     // LN output (half)
__device__ __half h_o  [(size_t)TOK * DMODEL];     // attention output (half)
__device__ __half h_act[(size_t)TOK * HIDDEN];     // GELU output (half)
// half weights, [N,K] K-major
__device__ __half w_pe  [(size_t)DMODEL * DMODEL];
__device__ __half w_qkv [(size_t)NLAYER * DMODEL * QKVN];
__device__ __half w_proj[(size_t)NLAYER * DMODEL * DMODEL];
__device__ __half w_f1  [(size_t)NLAYER * DMODEL * HIDDEN];
__device__ __half w_f2  [(size_t)NLAYER * HIDDEN * DMODEL];

// ---------------- helpers ----------------
__device__ __forceinline__ uint32_t smem_u32(const void* p) {
    uint32_t a;
    asm("{ .reg .u64 t; cvta.to.shared.u64 t, %1; cvt.u32.u64 %0, t; }" : "=r"(a) : "l"(p));
    return a;
}
__device__ __forceinline__ void cpasync16(void* dst, const void* src) {
    uint32_t d = (uint32_t)__cvta_generic_to_shared(dst);
    asm volatile("cp.async.cg.shared.global [%0], [%1], 16;" :: "r"(d), "l"(src));
}
__device__ __forceinline__ void ldmx4(uint32_t* r, uint32_t addr) {
    asm volatile("ldmatrix.sync.aligned.m8n8.x4.shared.b16 {%0,%1,%2,%3}, [%4];"
                 : "=r"(r[0]), "=r"(r[1]), "=r"(r[2]), "=r"(r[3]) : "r"(addr));
}
__device__ __forceinline__ void mma_f16(float* c, const uint32_t* a,
                                        uint32_t b0, uint32_t b1) {
    asm volatile(
        "mma.sync.aligned.m16n8k16.row.col.f32.f16.f16.f32 "
        "{%0,%1,%2,%3}, {%4,%5,%6,%7}, {%8,%9}, {%0,%1,%2,%3};"
        : "+f"(c[0]), "+f"(c[1]), "+f"(c[2]), "+f"(c[3])
        : "r"(a[0]), "r"(a[1]), "r"(a[2]), "r"(a[3]), "r"(b0), "r"(b1));
}

// ---------------- weight conversion ----------------
// transpose+convert: src fp32 [K,N] (per layer) -> dst half [N,K]
__global__ void tr_half_kernel(const float* __restrict__ src, __half* __restrict__ dst,
                               int K, int N) {
    __shared__ float t[32][33];
    size_t off = (size_t)blockIdx.z * K * N;
    src += off; dst += off;
    int kb = blockIdx.y * 32, nb = blockIdx.x * 32;
    for (int i = threadIdx.y; i < 32; i += 8)
        t[i][threadIdx.x] = src[(size_t)(kb + i) * N + nb + threadIdx.x];
    __syncthreads();
    for (int i = threadIdx.y; i < 32; i += 8)
        dst[(size_t)(nb + i) * K + kb + threadIdx.x] = __float2half_rn(t[threadIdx.x][i]);
}
// elementwise convert (conv_w is already [N,K])
__global__ void cvt_half_kernel(const float* __restrict__ src, __half* __restrict__ dst, int n) {
    int i = blockIdx.x * blockDim.x + threadIdx.x;
    if (i < n) dst[i] = __float2half_rn(src[i]);
}

// ---------------- patchify -> half ----------------
__global__ void patch_kernel(const float* __restrict__ x, __half* __restrict__ xp) {
    int idx = blockIdx.x * blockDim.x + threadIdx.x;
    if (idx >= TOK * DMODEL) return;
    int t = idx / DMODEL;
    int f = idx - t * DMODEL;
    int b = t / NPATCH;
    int p = t - b * NPATCH;
    int gy = p / GRID_, gx = p - gy * GRID_;
    int c  = f >> 8;
    int py = (f >> 4) & 15;
    int px = f & 15;
    xp[idx] = __float2half_rn(
        x[(((size_t)b * 3 + c) * IMG + gy * PSZ + py) * IMG + gx * PSZ + px]);
}

// ---------------- FP16 mma.sync GEMM ----------------
// C[M,N] = A[M,K] @ B[N,K]^T, A/B half, accum fp32.
// CTA 128x128, 4 warps (2x2 of 64x64), k-chunk 64, 3-stage ring,
// prefetch distance 1, SINGLE __syncthreads per iteration.
// OP 0: +bias -> fp32 ; 1: +bias+res -> fp32 ; 2: +bias,GELU -> HALF ; 3: +bias+pos -> fp32
#define KCH  64
#define ASTR 72                                  // halfs per row (144B), conflict-free
#define AB_HALFS (128 * ASTR)                    // 9216 halfs per operand
#define STAGE_BYTES (2 * AB_HALFS * 2)           // 36864
#define GSTAGES 3
#define GEMM_SMEM (GSTAGES * STAGE_BYTES)        // 110592 -> 2 CTAs = 216KB/SM

template <int OP>
__global__ void __launch_bounds__(128, 2)
gemm_fp16(const __half* __restrict__ A, const __half* __restrict__ B,
          const float* __restrict__ bias, const float* __restrict__ res,
          void* __restrict__ Cout, int M, int N, int K) {
    extern __shared__ __half sm[];
    const int tid = threadIdx.x;                  // 128 threads
    const int m0 = blockIdx.y * 128, n0 = blockIdx.x * 128;
    const int warp = tid >> 5, lane = tid & 31;
    const int wm = warp >> 1, wn = warp & 1;      // 2x2 warp grid
    const int g = lane >> 2, tg = lane & 3;

    const uint32_t smb = smem_u32(sm);
    uint32_t aAddr[4], bAddr[4];
#pragma unroll
    for (int mi = 0; mi < 4; mi++)
        aAddr[mi] = smb + ((wm * 64 + mi * 16 + (lane & 15)) * ASTR +
                           ((lane >> 4) & 1) * 8) * 2;
#pragma unroll
    for (int n2 = 0; n2 < 4; n2++)
        bAddr[n2] = smb + AB_HALFS * 2 +
                    ((wn * 64 + n2 * 16 + (lane & 7) + ((lane >> 4) & 1) * 8) * ASTR +
                     ((lane >> 3) & 1) * 8) * 2;

    float acc[4][8][4];
#pragma unroll
    for (int i = 0; i < 4; i++)
#pragma unroll
        for (int j = 0; j < 8; j++)
#pragma unroll
            for (int c = 0; c < 4; c++) acc[i][j][c] = 0.f;

    const int nIter = K >> 6;                     // k-chunk 64

    auto load_stage = [&](int it) {
        __half* As = sm + (it % GSTAGES) * (STAGE_BYTES / 2);
        __half* Bs = As + AB_HALFS;
        int k0 = it * KCH;
        const __half* Ag = A + (size_t)m0 * K + k0;
        const __half* Bg = B + (size_t)n0 * K + k0;
#pragma unroll
        for (int i = 0; i < 8; i++) {             // 128 rows x 8 chunks of 8 halfs
            int idx = tid + i * 128;
            int r = idx >> 3, c = (idx & 7) * 8;
            cpasync16(&As[r * ASTR + c], Ag + (size_t)r * K + c);
        }
#pragma unroll
        for (int i = 0; i < 8; i++) {
            int idx = tid + i * 128;
            int r = idx >> 3, c = (idx & 7) * 8;
            cpasync16(&Bs[r * ASTR + c], Bg + (size_t)r * K + c);
        }
        asm volatile("cp.async.commit_group;");
    };

    load_stage(0);

    for (int it = 0; it < nIter; it++) {
        if (it + 1 < nIter) {
            load_stage(it + 1);
            asm volatile("cp.async.wait_group 1;");
        } else {
            asm volatile("cp.async.wait_group 0;");
        }
        __syncthreads();                          // single barrier per iteration

        uint32_t stOff = (uint32_t)((it % GSTAGES) * STAGE_BYTES);
#pragma unroll
        for (int kk = 0; kk < 4; kk++) {          // four k=16 steps per 64-chunk
            uint32_t a[4][4], b[4][4];
#pragma unroll
            for (int mi = 0; mi < 4; mi++) ldmx4(a[mi], aAddr[mi] + stOff + kk * 32);
#pragma unroll
            for (int n2 = 0; n2 < 4; n2++) ldmx4(b[n2], bAddr[n2] + stOff + kk * 32);
#pragma unroll
            for (int mi = 0; mi < 4; mi++)
#pragma unroll
                for (int n2 = 0; n2 < 4; n2++) {
                    mma_f16(acc[mi][n2 * 2 + 0], a[mi], b[n2][0], b[n2][1]);
                    mma_f16(acc[mi][n2 * 2 + 1], a[mi], b[n2][2], b[n2][3]);
                }
        }
    }

    // ---- epilogue ----
    float* Cf = (float*)Cout;
    __half* Ch = (__half*)Cout;
#pragma unroll
    for (int mi = 0; mi < 4; mi++) {
        int r0 = m0 + wm * 64 + mi * 16 + g;
#pragma unroll
        for (int ni = 0; ni < 8; ni++) {
            int n = n0 + wn * 64 + ni * 8 + tg * 2;
            float2 bi = *(const float2*)(bias + n);
#pragma unroll
            for (int half = 0; half < 2; half++) {
                int m = r0 + half * 8;
                float v0 = acc[mi][ni][half * 2 + 0] + bi.x;
                float v1 = acc[mi][ni][half * 2 + 1] + bi.y;
                if (OP == 1) {
                    float2 rv = *(const float2*)(res + (size_t)m * N + n);
                    v0 += rv.x; v1 += rv.y;
                }
                if (OP == 3) {
                    float2 rv = *(const float2*)(res + (size_t)(m % NPATCH) * N + n);
                    v0 += rv.x; v1 += rv.y;
                }
                if (OP == 2) {
                    v0 = 0.5f * v0 * (1.0f + erff(v0 * 0.70710678118654752f));
                    v1 = 0.5f * v1 * (1.0f + erff(v1 * 0.70710678118654752f));
                    *(__half2*)(Ch + (size_t)m * N + n) = __floats2half2_rn(v0, v1);
                } else {
                    *(float2*)(Cf + (size_t)m * N + n) = make_float2(v0, v1);
                }
            }
        }
    }
}

// ---------------- attention: per (b, head) block (fp32 compute, half out) ----------------
#define KROW 68
#define SMEM_ATTN ((2 * 196 * KROW + 8 * KROW + 8 * 200) * 4)

__global__ void attn_kernel(const float* __restrict__ qkv, __half* __restrict__ o) {
    extern __shared__ float smA[];
    float* Ks = smA;
    float* Vs = Ks + 196 * KROW;
    float* Qs = Vs + 196 * KROW;
    float* Ps = Qs + 8 * KROW;

    int bh = blockIdx.x;
    int b = bh / NHEAD, h = bh - b * NHEAD;
    int tid = threadIdx.x;
    const float* base = qkv + (size_t)b * NPATCH * QKVN + h * HDIM;

    for (int i = tid; i < NPATCH * 16; i += 256) {
        int row = i >> 4, c4 = (i & 15) * 4;
        *(float4*)(&Ks[row * KROW + c4]) =
            *(const float4*)(base + (size_t)row * QKVN + DMODEL + c4);
        *(float4*)(&Vs[row * KROW + c4]) =
            *(const float4*)(base + (size_t)row * QKVN + 2 * DMODEL + c4);
    }
    __syncthreads();

    int w = tid >> 5, lane = tid & 31;
    const float scale = 0.125f;

    for (int q = w; q < NPATCH; q += 8) {
        for (int d = lane; d < HDIM; d += 32)
            Qs[w * KROW + d] = base[(size_t)q * QKVN + d];
        __syncwarp();

        float sc[7];
        float mx = -1e30f;
#pragma unroll
        for (int kk = 0; kk < 7; kk++) {
            int kidx = lane + kk * 32;
            float s = -1e30f;
            if (kidx < NPATCH) {
                const float4* kr = (const float4*)(&Ks[kidx * KROW]);
                const float4* qr = (const float4*)(&Qs[w * KROW]);
                float a = 0.f;
#pragma unroll
                for (int d4 = 0; d4 < 16; d4++) {
                    float4 kv = kr[d4], qv = qr[d4];
                    a += kv.x * qv.x + kv.y * qv.y + kv.z * qv.z + kv.w * qv.w;
                }
                s = a * scale;
            }
            sc[kk] = s;
            mx = fmaxf(mx, s);
        }
#pragma unroll
        for (int off = 16; off; off >>= 1)
            mx = fmaxf(mx, __shfl_xor_sync(0xffffffffu, mx, off));

        float sum = 0.f;
#pragma unroll
        for (int kk = 0; kk < 7; kk++) {
            int kidx = lane + kk * 32;
            float e = (kidx < NPATCH) ? __expf(sc[kk] - mx) : 0.f;
            sc[kk] = e;
            sum += e;
        }
#pragma unroll
        for (int off = 16; off; off >>= 1)
            sum += __shfl_xor_sync(0xffffffffu, sum, off);
        float inv = 1.f / sum;
#pragma unroll
        for (int kk = 0; kk < 7; kk++) {
            int kidx = lane + kk * 32;
            if (kidx < NPATCH) Ps[w * 200 + kidx] = sc[kk] * inv;
        }
        __syncwarp();

        float o0 = 0.f, o1 = 0.f;
        for (int k = 0; k < NPATCH; k++) {
            float p = Ps[w * 200 + k];
            o0 += p * Vs[k * KROW + lane];
            o1 += p * Vs[k * KROW + lane + 32];
        }
        size_t t = (size_t)b * NPATCH + q;
        o[t * DMODEL + h * HDIM + lane]      = __float2half_rn(o0);
        o[t * DMODEL + h * HDIM + lane + 32] = __float2half_rn(o1);
        __syncwarp();
    }
}

// ---------------- layernorm (templated output type) ----------------
template <typename TOUT>
__global__ void ln_kernel(const float* __restrict__ x, const float* __restrict__ w,
                          const float* __restrict__ bb, TOUT* __restrict__ y) {
    int t = blockIdx.x;
    const float* xr = x + (size_t)t * DMODEL;
    int tid = threadIdx.x;
    float v[3];
    float s = 0.f, ss = 0.f;
#pragma unroll
    for (int i = 0; i < 3; i++) {
        v[i] = xr[tid + i * 256];
        s += v[i];
        ss += v[i] * v[i];
    }
    __shared__ float redS[8], redQ[8];
#pragma unroll
    for (int off = 16; off; off >>= 1) {
        s  += __shfl_xor_sync(0xffffffffu, s,  off);
        ss += __shfl_xor_sync(0xffffffffu, ss, off);
    }
    if ((tid & 31) == 0) { redS[tid >> 5] = s; redQ[tid >> 5] = ss; }
    __syncthreads();
    if (tid == 0) {
        float a = 0.f, b2 = 0.f;
#pragma unroll
        for (int i = 0; i < 8; i++) { a += redS[i]; b2 += redQ[i]; }
        float mean = a * (1.0f / DMODEL);
        float var = b2 * (1.0f / DMODEL) - mean * mean;
        redS[0] = mean;
        redQ[0] = rsqrtf(var + 1e-5f);
    }
    __syncthreads();
    float mean = redS[0], rstd = redQ[0];
    TOUT* yr = y + (size_t)t * DMODEL;
#pragma unroll
    for (int i = 0; i < 3; i++) {
        int c = tid + i * 256;
        float o = (v[i] - mean) * rstd * w[c] + bb[c];
        yr[c] = (TOUT)o;
    }
}

// ---------------- launch ----------------
extern "C" void kernel_launch(void* const* d_in, const int* in_sizes, int n_in,
                              void* d_out, int out_size) {
    const float* x      = (const float*)d_in[0];
    const float* conv_w = (const float*)d_in[1];
    const float* conv_b = (const float*)d_in[2];
    const float* pos    = (const float*)d_in[3];
    const float* ln1w   = (const float*)d_in[4];
    const float* ln1b   = (const float*)d_in[5];
    const float* qkvw   = (const float*)d_in[6];
    const float* qkvb   = (const float*)d_in[7];
    const float* projw  = (const float*)d_in[8];
    const float* projb  = (const float*)d_in[9];
    const float* ln2w   = (const float*)d_in[10];
    const float* ln2b   = (const float*)d_in[11];
    const float* f1w    = (const float*)d_in[12];
    const float* f1b    = (const float*)d_in[13];
    const float* f2w    = (const float*)d_in[14];
    const float* f2b    = (const float*)d_in[15];
    const float* lnfw   = (const float*)d_in[16];
    const float* lnfb   = (const float*)d_in[17];
    float* out = (float*)d_out;

    float *h, *qkv;
    __half *xp, *y, *o, *act, *wpe, *rqkvw, *rprojw, *rf1w, *rf2w;
    cudaGetSymbolAddress((void**)&h,   g_h);
    cudaGetSymbolAddress((void**)&qkv, g_qkv);
    cudaGetSymbolAddress((void**)&xp,  h_xp);
    cudaGetSymbolAddress((void**)&y,   h_y);
    cudaGetSymbolAddress((void**)&o,   h_o);
    cudaGetSymbolAddress((void**)&act, h_act);
    cudaGetSymbolAddress((void**)&wpe, w_pe);
    cudaGetSymbolAddress((void**)&rqkvw,  w_qkv);
    cudaGetSymbolAddress((void**)&rprojw, w_proj);
    cudaGetSymbolAddress((void**)&rf1w,   w_f1);
    cudaGetSymbolAddress((void**)&rf2w,   w_f2);

    cudaFuncSetAttribute(attn_kernel, cudaFuncAttributeMaxDynamicSharedMemorySize, SMEM_ATTN);
    cudaFuncSetAttribute(gemm_fp16<0>, cudaFuncAttributeMaxDynamicSharedMemorySize, GEMM_SMEM);
    cudaFuncSetAttribute(gemm_fp16<1>, cudaFuncAttributeMaxDynamicSharedMemorySize, GEMM_SMEM);
    cudaFuncSetAttribute(gemm_fp16<2>, cudaFuncAttributeMaxDynamicSharedMemorySize, GEMM_SMEM);
    cudaFuncSetAttribute(gemm_fp16<3>, cudaFuncAttributeMaxDynamicSharedMemorySize, GEMM_SMEM);

    // weights -> half, [N,K] (transpose), once per launch; conv_w is already [N,K]
    {
        dim3 blk(32, 8);
        tr_half_kernel<<<dim3(QKVN  / 32, DMODEL / 32, NLAYER), blk>>>(qkvw,  rqkvw,  DMODEL, QKVN);
        tr_half_kernel<<<dim3(DMODEL/ 32, DMODEL / 32, NLAYER), blk>>>(projw, rprojw, DMODEL, DMODEL);
        tr_half_kernel<<<dim3(HIDDEN/ 32, DMODEL / 32, NLAYER), blk>>>(f1w,   rf1w,   DMODEL, HIDDEN);
        tr_half_kernel<<<dim3(DMODEL/ 32, HIDDEN / 32, NLAYER), blk>>>(f2w,   rf2w,   HIDDEN, DMODEL);
        int n = DMODEL * DMODEL;
        cvt_half_kernel<<<(n + 255) / 256, 256>>>(conv_w, wpe, n);
    }

    // patchify + patch-embed GEMM (+bias +pos_embed)
    patch_kernel<<<(TOK * DMODEL + 255) / 256, 256>>>(x, xp);
    gemm_fp16<3><<<dim3(DMODEL / 128, TOK / 128), 128, GEMM_SMEM>>>(
        xp, wpe, conv_b, pos, h, TOK, DMODEL, DMODEL);

    for (int l = 0; l < NLAYER; l++) {
        ln_kernel<__half><<<TOK, 256>>>(h, ln1w + (size_t)l * DMODEL, ln1b + (size_t)l * DMODEL, y);
        gemm_fp16<0><<<dim3(QKVN / 128, TOK / 128), 128, GEMM_SMEM>>>(
            y, rqkvw + (size_t)l * DMODEL * QKVN, qkvb + (size_t)l * QKVN, nullptr, qkv,
            TOK, QKVN, DMODEL);
        attn_kernel<<<BATCH * NHEAD, 256, SMEM_ATTN>>>(qkv, o);
        gemm_fp16<1><<<dim3(DMODEL / 128, TOK / 128), 128, GEMM_SMEM>>>(
            o, rprojw + (size_t)l * DMODEL * DMODEL, projb + (size_t)l * DMODEL, h, h,
            TOK, DMODEL, DMODEL);
        ln_kernel<__half><<<TOK, 256>>>(h, ln2w + (size_t)l * DMODEL, ln2b + (size_t)l * DMODEL, y);
        gemm_fp16<2><<<dim3(HIDDEN / 128, TOK / 128), 128, GEMM_SMEM>>>(
            y, rf1w + (size_t)l * DMODEL * HIDDEN, f1b + (size_t)l * HIDDEN, nullptr, act,
            TOK, HIDDEN, DMODEL);
        gemm_fp16<1><<<dim3(DMODEL / 128, TOK / 128), 128, GEMM_SMEM>>>(
            act, rf2w + (size_t)l * HIDDEN * DMODEL, f2b + (size_t)l * DMODEL, h, h,
            TOK, DMODEL, HIDDEN);
    }
    ln_kernel<float><<<TOK, 256>>>(h, lnfw, lnfb, out);
}

// round 13
// speedup vs baseline: 7.5599x; 1.7537x over previous
#include <cuda_runtime.h>
#include <cuda_fp16.h>
#include <math.h>
#include <stdint.h>

// ---------------- problem constants ----------------
#define BATCH   32
#define NPATCH  196
#define TOK     (BATCH * NPATCH)   // 6272
#define DMODEL  768
#define NHEAD   12
#define HDIM    64
#define NLAYER  12
#define HIDDEN  3072
#define QKVN    (3 * DMODEL)       // 2304
#define IMG     224
#define PSZ     16
#define GRID_   14

// ---------------- scratch (no allocations allowed) ----------------
__device__ float  g_h  [(size_t)TOK * DMODEL];     // residual stream (fp32)
__device__ __half h_qkv[(size_t)TOK * QKVN];       // qkv (half)
__device__ __half h_xp [(size_t)TOK * DMODEL];     // patchified input (half)
__device__ __half h_y  [(size_t)TOK * DMODEL];     // LN output (half)
__device__ __half h_o  [(size_t)TOK * DMODEL];     // attention output (half)
__device__ __half h_act[(size_t)TOK * HIDDEN];     // GELU output (half)
// half weights, [N,K] K-major
__device__ __half w_pe  [(size_t)DMODEL * DMODEL];
__device__ __half w_qkv [(size_t)NLAYER * DMODEL * QKVN];
__device__ __half w_proj[(size_t)NLAYER * DMODEL * DMODEL];
__device__ __half w_f1  [(size_t)NLAYER * DMODEL * HIDDEN];
__device__ __half w_f2  [(size_t)NLAYER * HIDDEN * DMODEL];

// ---------------- helpers ----------------
__device__ __forceinline__ uint32_t smem_u32(const void* p) {
    uint32_t a;
    asm("{ .reg .u64 t; cvta.to.shared.u64 t, %1; cvt.u32.u64 %0, t; }" : "=r"(a) : "l"(p));
    return a;
}
__device__ __forceinline__ void cpasync16(void* dst, const void* src) {
    uint32_t d = (uint32_t)__cvta_generic_to_shared(dst);
    asm volatile("cp.async.cg.shared.global [%0], [%1], 16;" :: "r"(d), "l"(src));
}
__device__ __forceinline__ void ldmx4(uint32_t* r, uint32_t addr) {
    asm volatile("ldmatrix.sync.aligned.m8n8.x4.shared.b16 {%0,%1,%2,%3}, [%4];"
                 : "=r"(r[0]), "=r"(r[1]), "=r"(r[2]), "=r"(r[3]) : "r"(addr));
}
__device__ __forceinline__ void mma_f16(float* c, const uint32_t* a,
                                        uint32_t b0, uint32_t b1) {
    asm volatile(
        "mma.sync.aligned.m16n8k16.row.col.f32.f16.f16.f32 "
        "{%0,%1,%2,%3}, {%4,%5,%6,%7}, {%8,%9}, {%0,%1,%2,%3};"
        : "+f"(c[0]), "+f"(c[1]), "+f"(c[2]), "+f"(c[3])
        : "r"(a[0]), "r"(a[1]), "r"(a[2]), "r"(a[3]), "r"(b0), "r"(b1));
}
__device__ __forceinline__ uint32_t h2u(float x, float y) {
    __half2 h = __floats2half2_rn(x, y);
    return *(uint32_t*)&h;
}

// ---------------- weight conversion ----------------
__global__ void tr_half_kernel(const float* __restrict__ src, __half* __restrict__ dst,
                               int K, int N) {
    __shared__ float t[32][33];
    size_t off = (size_t)blockIdx.z * K * N;
    src += off; dst += off;
    int kb = blockIdx.y * 32, nb = blockIdx.x * 32;
    for (int i = threadIdx.y; i < 32; i += 8)
        t[i][threadIdx.x] = src[(size_t)(kb + i) * N + nb + threadIdx.x];
    __syncthreads();
    for (int i = threadIdx.y; i < 32; i += 8)
        dst[(size_t)(nb + i) * K + kb + threadIdx.x] = __float2half_rn(t[threadIdx.x][i]);
}
__global__ void cvt_half_kernel(const float* __restrict__ src, __half* __restrict__ dst, int n) {
    int i = blockIdx.x * blockDim.x + threadIdx.x;
    if (i < n) dst[i] = __float2half_rn(src[i]);
}

// ---------------- patchify -> half ----------------
__global__ void patch_kernel(const float* __restrict__ x, __half* __restrict__ xp) {
    int idx = blockIdx.x * blockDim.x + threadIdx.x;
    if (idx >= TOK * DMODEL) return;
    int t = idx / DMODEL;
    int f = idx - t * DMODEL;
    int b = t / NPATCH;
    int p = t - b * NPATCH;
    int gy = p / GRID_, gx = p - gy * GRID_;
    int c  = f >> 8;
    int py = (f >> 4) & 15;
    int px = f & 15;
    xp[idx] = __float2half_rn(
        x[(((size_t)b * 3 + c) * IMG + gy * PSZ + py) * IMG + gx * PSZ + px]);
}

// ---------------- FP16 mma.sync GEMM ----------------
// OP 0: +bias -> HALF ; 1: +bias+res -> fp32 ; 2: +bias,GELU -> HALF ; 3: +bias+pos -> fp32
#define KCH  64
#define ASTR 72
#define AB_HALFS (128 * ASTR)
#define STAGE_BYTES (2 * AB_HALFS * 2)           // 36864
#define GSTAGES 3
#define GEMM_SMEM (GSTAGES * STAGE_BYTES)        // 110592

template <int OP>
__global__ void __launch_bounds__(128, 2)
gemm_fp16(const __half* __restrict__ A, const __half* __restrict__ B,
          const float* __restrict__ bias, const float* __restrict__ res,
          void* __restrict__ Cout, int M, int N, int K) {
    extern __shared__ __half sm[];
    const int tid = threadIdx.x;
    const int m0 = blockIdx.y * 128, n0 = blockIdx.x * 128;
    const int warp = tid >> 5, lane = tid & 31;
    const int wm = warp >> 1, wn = warp & 1;
    const int g = lane >> 2, tg = lane & 3;

    const uint32_t smb = smem_u32(sm);
    uint32_t aAddr[4], bAddr[4];
#pragma unroll
    for (int mi = 0; mi < 4; mi++)
        aAddr[mi] = smb + ((wm * 64 + mi * 16 + (lane & 15)) * ASTR +
                           ((lane >> 4) & 1) * 8) * 2;
#pragma unroll
    for (int n2 = 0; n2 < 4; n2++)
        bAddr[n2] = smb + AB_HALFS * 2 +
                    ((wn * 64 + n2 * 16 + (lane & 7) + ((lane >> 4) & 1) * 8) * ASTR +
                     ((lane >> 3) & 1) * 8) * 2;

    float acc[4][8][4];
#pragma unroll
    for (int i = 0; i < 4; i++)
#pragma unroll
        for (int j = 0; j < 8; j++)
#pragma unroll
            for (int c = 0; c < 4; c++) acc[i][j][c] = 0.f;

    const int nIter = K >> 6;

    auto load_stage = [&](int it) {
        __half* As = sm + (it % GSTAGES) * (STAGE_BYTES / 2);
        __half* Bs = As + AB_HALFS;
        int k0 = it * KCH;
        const __half* Ag = A + (size_t)m0 * K + k0;
        const __half* Bg = B + (size_t)n0 * K + k0;
#pragma unroll
        for (int i = 0; i < 8; i++) {
            int idx = tid + i * 128;
            int r = idx >> 3, c = (idx & 7) * 8;
            cpasync16(&As[r * ASTR + c], Ag + (size_t)r * K + c);
        }
#pragma unroll
        for (int i = 0; i < 8; i++) {
            int idx = tid + i * 128;
            int r = idx >> 3, c = (idx & 7) * 8;
            cpasync16(&Bs[r * ASTR + c], Bg + (size_t)r * K + c);
        }
        asm volatile("cp.async.commit_group;");
    };

    load_stage(0);

    for (int it = 0; it < nIter; it++) {
        if (it + 1 < nIter) {
            load_stage(it + 1);
            asm volatile("cp.async.wait_group 1;");
        } else {
            asm volatile("cp.async.wait_group 0;");
        }
        __syncthreads();

        uint32_t stOff = (uint32_t)((it % GSTAGES) * STAGE_BYTES);
#pragma unroll
        for (int kk = 0; kk < 4; kk++) {
            uint32_t a[4][4], b[4][4];
#pragma unroll
            for (int mi = 0; mi < 4; mi++) ldmx4(a[mi], aAddr[mi] + stOff + kk * 32);
#pragma unroll
            for (int n2 = 0; n2 < 4; n2++) ldmx4(b[n2], bAddr[n2] + stOff + kk * 32);
#pragma unroll
            for (int mi = 0; mi < 4; mi++)
#pragma unroll
                for (int n2 = 0; n2 < 4; n2++) {
                    mma_f16(acc[mi][n2 * 2 + 0], a[mi], b[n2][0], b[n2][1]);
                    mma_f16(acc[mi][n2 * 2 + 1], a[mi], b[n2][2], b[n2][3]);
                }
        }
    }

    // ---- epilogue ----
    float* Cf = (float*)Cout;
    __half* Ch = (__half*)Cout;
#pragma unroll
    for (int mi = 0; mi < 4; mi++) {
        int r0 = m0 + wm * 64 + mi * 16 + g;
#pragma unroll
        for (int ni = 0; ni < 8; ni++) {
            int n = n0 + wn * 64 + ni * 8 + tg * 2;
            float2 bi = *(const float2*)(bias + n);
#pragma unroll
            for (int half = 0; half < 2; half++) {
                int m = r0 + half * 8;
                float v0 = acc[mi][ni][half * 2 + 0] + bi.x;
                float v1 = acc[mi][ni][half * 2 + 1] + bi.y;
                if (OP == 1) {
                    float2 rv = *(const float2*)(res + (size_t)m * N + n);
                    v0 += rv.x; v1 += rv.y;
                }
                if (OP == 3) {
                    float2 rv = *(const float2*)(res + (size_t)(m % NPATCH) * N + n);
                    v0 += rv.x; v1 += rv.y;
                }
                if (OP == 2) {
                    v0 = 0.5f * v0 * (1.0f + erff(v0 * 0.70710678118654752f));
                    v1 = 0.5f * v1 * (1.0f + erff(v1 * 0.70710678118654752f));
                }
                if (OP == 0 || OP == 2) {
                    *(__half2*)(Ch + (size_t)m * N + n) = __floats2half2_rn(v0, v1);
                } else {
                    *(float2*)(Cf + (size_t)m * N + n) = make_float2(v0, v1);
                }
            }
        }
    }
}

// ---------------- attention: tensor-core flash-lite, one CTA per (b,h) ----------------
// smem: Qs[208][72] half, Ks[208][72] half, VT[64][216] half (V transposed, pad zeroed)
#define QSTR 72
#define VSTR 216
#define QS_OFF 0
#define KS_OFF (208 * QSTR)              // 14976 halfs
#define VT_OFF (2 * 208 * QSTR)          // 29952 halfs
#define SMEM_ATTN ((VT_OFF + 64 * VSTR) * 2)   // 87552 bytes

__global__ void __launch_bounds__(256, 1)
attn_kernel(const __half* __restrict__ qkv, __half* __restrict__ o) {
    extern __shared__ __half smh[];
    const int tid = threadIdx.x;
    const int bh = blockIdx.x;
    const int b = bh / NHEAD, hh = bh - b * NHEAD;
    const __half* base = qkv + (size_t)b * NPATCH * QKVN + hh * HDIM;

    // zero VT (pad cols 196..215 must be 0 so 0*garbage can't poison PV)
    for (int i = tid; i < 64 * VSTR / 8; i += 256)
        ((uint4*)(smh + VT_OFF))[i] = make_uint4(0u, 0u, 0u, 0u);
    __syncthreads();
    // fill Qs, Ks (rows >=196 clamped to 195: finite, masked later)
    for (int i = tid; i < 208 * 8; i += 256) {
        int r = i >> 3, c = (i & 7) * 8;
        int row = r < NPATCH ? r : NPATCH - 1;
        const __half* src = base + (size_t)row * QKVN;
        *(uint4*)(smh + QS_OFF + r * QSTR + c) = *(const uint4*)(src + c);
        *(uint4*)(smh + KS_OFF + r * QSTR + c) = *(const uint4*)(src + DMODEL + c);
    }
    // V transpose: VT[d][k]
    for (int i = tid; i < NPATCH * 8; i += 256) {
        int kidx = i >> 3, c8 = (i & 7) * 8;
        uint4 v = *(const uint4*)(base + (size_t)kidx * QKVN + 2 * DMODEL + c8);
        const __half* vh = (const __half*)&v;
#pragma unroll
        for (int d = 0; d < 8; d++)
            smh[VT_OFF + (c8 + d) * VSTR + kidx] = vh[d];
    }
    __syncthreads();

    const int warp = tid >> 5, lane = tid & 31;
    const int g = lane >> 2, tg = lane & 3;
    const uint32_t smb = smem_u32(smh);
    const uint32_t qsB = smb + QS_OFF * 2;
    const uint32_t ksB = smb + KS_OFF * 2;
    const uint32_t vtB = smb + VT_OFF * 2;

    const uint32_t aRow = ((lane & 15) * QSTR + ((lane >> 4) & 1) * 8) * 2;
    const uint32_t bRowK = (((lane & 7) + ((lane >> 4) & 1) * 8) * QSTR + ((lane >> 3) & 1) * 8) * 2;
    const uint32_t bRowV = (((lane & 7) + ((lane >> 4) & 1) * 8) * VSTR + ((lane >> 3) & 1) * 8) * 2;

    for (int qc = warp; qc < 13; qc += 8) {
        int q0 = qc * 16;
        uint32_t qa[4][4];
#pragma unroll
        for (int kk = 0; kk < 4; kk++)
            ldmx4(qa[kk], qsB + q0 * QSTR * 2 + aRow + kk * 32);

        float sacc[26][4];
#pragma unroll
        for (int j = 0; j < 26; j++)
#pragma unroll
            for (int c = 0; c < 4; c++) sacc[j][c] = 0.f;

#pragma unroll
        for (int n2 = 0; n2 < 13; n2++) {
#pragma unroll
            for (int kk = 0; kk < 4; kk++) {
                uint32_t bk[4];
                ldmx4(bk, ksB + n2 * 16 * QSTR * 2 + bRowK + kk * 32);
                mma_f16(sacc[n2 * 2 + 0], qa[kk], bk[0], bk[1]);
                mma_f16(sacc[n2 * 2 + 1], qa[kk], bk[2], bk[3]);
            }
        }

        // softmax over k cols (cols >=196 masked); scale 0.125 folded into exp
        float m0 = -1e30f, m1 = -1e30f;
#pragma unroll
        for (int j = 0; j < 25; j++) {
            bool v = (j < 24) || (tg < 2);
            if (v) {
                m0 = fmaxf(m0, fmaxf(sacc[j][0], sacc[j][1]));
                m1 = fmaxf(m1, fmaxf(sacc[j][2], sacc[j][3]));
            }
        }
        m0 = fmaxf(m0, __shfl_xor_sync(0xffffffffu, m0, 1));
        m0 = fmaxf(m0, __shfl_xor_sync(0xffffffffu, m0, 2));
        m1 = fmaxf(m1, __shfl_xor_sync(0xffffffffu, m1, 1));
        m1 = fmaxf(m1, __shfl_xor_sync(0xffffffffu, m1, 2));

        float l0 = 0.f, l1 = 0.f;
#pragma unroll
        for (int j = 0; j < 26; j++) {
            bool v = (j < 24) || (j == 24 && tg < 2);
            float e0 = v ? __expf(0.125f * (sacc[j][0] - m0)) : 0.f;
            float e1 = v ? __expf(0.125f * (sacc[j][1] - m0)) : 0.f;
            float e2 = v ? __expf(0.125f * (sacc[j][2] - m1)) : 0.f;
            float e3 = v ? __expf(0.125f * (sacc[j][3] - m1)) : 0.f;
            sacc[j][0] = e0; sacc[j][1] = e1; sacc[j][2] = e2; sacc[j][3] = e3;
            l0 += e0 + e1; l1 += e2 + e3;
        }
        l0 += __shfl_xor_sync(0xffffffffu, l0, 1);
        l0 += __shfl_xor_sync(0xffffffffu, l0, 2);
        l1 += __shfl_xor_sync(0xffffffffu, l1, 1);
        l1 += __shfl_xor_sync(0xffffffffu, l1, 2);
        float i0 = 1.f / l0, i1 = 1.f / l1;

        // repack S c-frags -> P a-frags (normalize in the pack)
        uint32_t pa[13][4];
#pragma unroll
        for (int nt = 0; nt < 13; nt++) {
            pa[nt][0] = h2u(sacc[2 * nt][0] * i0, sacc[2 * nt][1] * i0);
            pa[nt][1] = h2u(sacc[2 * nt][2] * i1, sacc[2 * nt][3] * i1);
            pa[nt][2] = h2u(sacc[2 * nt + 1][0] * i0, sacc[2 * nt + 1][1] * i0);
            pa[nt][3] = h2u(sacc[2 * nt + 1][2] * i1, sacc[2 * nt + 1][3] * i1);
        }

        float oacc[8][4];
#pragma unroll
        for (int j = 0; j < 8; j++)
#pragma unroll
            for (int c = 0; c < 4; c++) oacc[j][c] = 0.f;

#pragma unroll
        for (int dn2 = 0; dn2 < 4; dn2++) {
#pragma unroll
            for (int nt = 0; nt < 13; nt++) {
                uint32_t bv[4];
                ldmx4(bv, vtB + dn2 * 16 * VSTR * 2 + bRowV + nt * 32);
                mma_f16(oacc[dn2 * 2 + 0], pa[nt], bv[0], bv[1]);
                mma_f16(oacc[dn2 * 2 + 1], pa[nt], bv[2], bv[3]);
            }
        }

        int r0 = q0 + g, r1 = q0 + g + 8;
        __half* ob = o + (size_t)b * NPATCH * DMODEL + hh * HDIM;
#pragma unroll
        for (int j8 = 0; j8 < 8; j8++) {
            int col = j8 * 8 + 2 * tg;
            if (r0 < NPATCH)
                *(__half2*)(ob + (size_t)r0 * DMODEL + col) =
                    __floats2half2_rn(oacc[j8][0], oacc[j8][1]);
            if (r1 < NPATCH)
                *(__half2*)(ob + (size_t)r1 * DMODEL + col) =
                    __floats2half2_rn(oacc[j8][2], oacc[j8][3]);
        }
    }
}

// ---------------- layernorm (templated output type) ----------------
template <typename TOUT>
__global__ void ln_kernel(const float* __restrict__ x, const float* __restrict__ w,
                          const float* __restrict__ bb, TOUT* __restrict__ y) {
    int t = blockIdx.x;
    const float* xr = x + (size_t)t * DMODEL;
    int tid = threadIdx.x;
    float v[3];
    float s = 0.f, ss = 0.f;
#pragma unroll
    for (int i = 0; i < 3; i++) {
        v[i] = xr[tid + i * 256];
        s += v[i];
        ss += v[i] * v[i];
    }
    __shared__ float redS[8], redQ[8];
#pragma unroll
    for (int off = 16; off; off >>= 1) {
        s  += __shfl_xor_sync(0xffffffffu, s,  off);
        ss += __shfl_xor_sync(0xffffffffu, ss, off);
    }
    if ((tid & 31) == 0) { redS[tid >> 5] = s; redQ[tid >> 5] = ss; }
    __syncthreads();
    if (tid == 0) {
        float a = 0.f, b2 = 0.f;
#pragma unroll
        for (int i = 0; i < 8; i++) { a += redS[i]; b2 += redQ[i]; }
        float mean = a * (1.0f / DMODEL);
        float var = b2 * (1.0f / DMODEL) - mean * mean;
        redS[0] = mean;
        redQ[0] = rsqrtf(var + 1e-5f);
    }
    __syncthreads();
    float mean = redS[0], rstd = redQ[0];
    TOUT* yr = y + (size_t)t * DMODEL;
#pragma unroll
    for (int i = 0; i < 3; i++) {
        int c = tid + i * 256;
        float o = (v[i] - mean) * rstd * w[c] + bb[c];
        yr[c] = (TOUT)o;
    }
}

// ---------------- launch ----------------
extern "C" void kernel_launch(void* const* d_in, const int* in_sizes, int n_in,
                              void* d_out, int out_size) {
    const float* x      = (const float*)d_in[0];
    const float* conv_w = (const float*)d_in[1];
    const float* conv_b = (const float*)d_in[2];
    const float* pos    = (const float*)d_in[3];
    const float* ln1w   = (const float*)d_in[4];
    const float* ln1b   = (const float*)d_in[5];
    const float* qkvw   = (const float*)d_in[6];
    const float* qkvb   = (const float*)d_in[7];
    const float* projw  = (const float*)d_in[8];
    const float* projb  = (const float*)d_in[9];
    const float* ln2w   = (const float*)d_in[10];
    const float* ln2b   = (const float*)d_in[11];
    const float* f1w    = (const float*)d_in[12];
    const float* f1b    = (const float*)d_in[13];
    const float* f2w    = (const float*)d_in[14];
    const float* f2b    = (const float*)d_in[15];
    const float* lnfw   = (const float*)d_in[16];
    const float* lnfb   = (const float*)d_in[17];
    float* out = (float*)d_out;

    float* h;
    __half *qkv, *xp, *y, *o, *act, *wpe, *rqkvw, *rprojw, *rf1w, *rf2w;
    cudaGetSymbolAddress((void**)&h,   g_h);
    cudaGetSymbolAddress((void**)&qkv, h_qkv);
    cudaGetSymbolAddress((void**)&xp,  h_xp);
    cudaGetSymbolAddress((void**)&y,   h_y);
    cudaGetSymbolAddress((void**)&o,   h_o);
    cudaGetSymbolAddress((void**)&act, h_act);
    cudaGetSymbolAddress((void**)&wpe, w_pe);
    cudaGetSymbolAddress((void**)&rqkvw,  w_qkv);
    cudaGetSymbolAddress((void**)&rprojw, w_proj);
    cudaGetSymbolAddress((void**)&rf1w,   w_f1);
    cudaGetSymbolAddress((void**)&rf2w,   w_f2);

    cudaFuncSetAttribute(attn_kernel, cudaFuncAttributeMaxDynamicSharedMemorySize, SMEM_ATTN);
    cudaFuncSetAttribute(gemm_fp16<0>, cudaFuncAttributeMaxDynamicSharedMemorySize, GEMM_SMEM);
    cudaFuncSetAttribute(gemm_fp16<1>, cudaFuncAttributeMaxDynamicSharedMemorySize, GEMM_SMEM);
    cudaFuncSetAttribute(gemm_fp16<2>, cudaFuncAttributeMaxDynamicSharedMemorySize, GEMM_SMEM);
    cudaFuncSetAttribute(gemm_fp16<3>, cudaFuncAttributeMaxDynamicSharedMemorySize, GEMM_SMEM);

    // weights -> half, [N,K] (transpose), once per launch; conv_w is already [N,K]
    {
        dim3 blk(32, 8);
        tr_half_kernel<<<dim3(QKVN  / 32, DMODEL / 32, NLAYER), blk>>>(qkvw,  rqkvw,  DMODEL, QKVN);
        tr_half_kernel<<<dim3(DMODEL/ 32, DMODEL / 32, NLAYER), blk>>>(projw, rprojw, DMODEL, DMODEL);
        tr_half_kernel<<<dim3(HIDDEN/ 32, DMODEL / 32, NLAYER), blk>>>(f1w,   rf1w,   DMODEL, HIDDEN);
        tr_half_kernel<<<dim3(DMODEL/ 32, HIDDEN / 32, NLAYER), blk>>>(f2w,   rf2w,   HIDDEN, DMODEL);
        int n = DMODEL * DMODEL;
        cvt_half_kernel<<<(n + 255) / 256, 256>>>(conv_w, wpe, n);
    }

    // patchify + patch-embed GEMM (+bias +pos_embed)
    patch_kernel<<<(TOK * DMODEL + 255) / 256, 256>>>(x, xp);
    gemm_fp16<3><<<dim3(DMODEL / 128, TOK / 128), 128, GEMM_SMEM>>>(
        xp, wpe, conv_b, pos, h, TOK, DMODEL, DMODEL);

    for (int l = 0; l < NLAYER; l++) {
        ln_kernel<__half><<<TOK, 256>>>(h, ln1w + (size_t)l * DMODEL, ln1b + (size_t)l * DMODEL, y);
        gemm_fp16<0><<<dim3(QKVN / 128, TOK / 128), 128, GEMM_SMEM>>>(
            y, rqkvw + (size_t)l * DMODEL * QKVN, qkvb + (size_t)l * QKVN, nullptr, qkv,
            TOK, QKVN, DMODEL);
        attn_kernel<<<BATCH * NHEAD, 256, SMEM_ATTN>>>(qkv, o);
        gemm_fp16<1><<<dim3(DMODEL / 128, TOK / 128), 128, GEMM_SMEM>>>(
            o, rprojw + (size_t)l * DMODEL * DMODEL, projb + (size_t)l * DMODEL, h, h,
            TOK, DMODEL, DMODEL);
        ln_kernel<__half><<<TOK, 256>>>(h, ln2w + (size_t)l * DMODEL, ln2b + (size_t)l * DMODEL, y);
        gemm_fp16<2><<<dim3(HIDDEN / 128, TOK / 128), 128, GEMM_SMEM>>>(
            y, rf1w + (size_t)l * DMODEL * HIDDEN, f1b + (size_t)l * HIDDEN, nullptr, act,
            TOK, HIDDEN, DMODEL);
        gemm_fp16<1><<<dim3(DMODEL / 128, TOK / 128), 128, GEMM_SMEM>>>(
            act, rf2w + (size_t)l * HIDDEN * DMODEL, f2b + (size_t)l * DMODEL, h, h,
            TOK, DMODEL, HIDDEN);
    }
    ln_kernel<float><<<TOK, 256>>>(h, lnfw, lnfb, out);
}

// round 14
// speedup vs baseline: 7.8502x; 1.0384x over previous
#include <cuda_runtime.h>
#include <cuda_fp16.h>
#include <math.h>
#include <stdint.h>

// ---------------- problem constants ----------------
#define BATCH   32
#define NPATCH  196
#define TOK     (BATCH * NPATCH)   // 6272
#define DMODEL  768
#define NHEAD   12
#define HDIM    64
#define NLAYER  12
#define HIDDEN  3072
#define QKVN    (3 * DMODEL)       // 2304
#define IMG     224
#define PSZ     16
#define GRID_   14

// ---------------- scratch (no allocations allowed) ----------------
__device__ float  g_h  [(size_t)TOK * DMODEL];     // residual stream (fp32)
__device__ __half h_qkv[(size_t)TOK * QKVN];       // qkv (half)
__device__ __half h_xp [(size_t)TOK * DMODEL];     // patchified input (half)
__device__ __half h_y  [(size_t)TOK * DMODEL];     // LN output (half)
__device__ __half h_o  [(size_t)TOK * DMODEL];     // attention output (half)
__device__ __half h_act[(size_t)TOK * HIDDEN];     // GELU output (half)
// half weights, native [K,N] layout (B operand via ldmatrix.trans)
__device__ __half w_pe  [(size_t)DMODEL * DMODEL];   // conv_w transposed -> [K,N]
__device__ __half w_qkv [(size_t)NLAYER * DMODEL * QKVN];
__device__ __half w_proj[(size_t)NLAYER * DMODEL * DMODEL];
__device__ __half w_f1  [(size_t)NLAYER * DMODEL * HIDDEN];
__device__ __half w_f2  [(size_t)NLAYER * HIDDEN * DMODEL];

// ---------------- helpers ----------------
__device__ __forceinline__ uint32_t smem_u32(const void* p) {
    uint32_t a;
    asm("{ .reg .u64 t; cvta.to.shared.u64 t, %1; cvt.u32.u64 %0, t; }" : "=r"(a) : "l"(p));
    return a;
}
__device__ __forceinline__ void cpasync16(void* dst, const void* src) {
    uint32_t d = (uint32_t)__cvta_generic_to_shared(dst);
    asm volatile("cp.async.cg.shared.global [%0], [%1], 16;" :: "r"(d), "l"(src));
}
__device__ __forceinline__ void ldmx4(uint32_t* r, uint32_t addr) {
    asm volatile("ldmatrix.sync.aligned.m8n8.x4.shared.b16 {%0,%1,%2,%3}, [%4];"
                 : "=r"(r[0]), "=r"(r[1]), "=r"(r[2]), "=r"(r[3]) : "r"(addr));
}
__device__ __forceinline__ void ldmx4t(uint32_t* r, uint32_t addr) {
    asm volatile("ldmatrix.sync.aligned.m8n8.x4.trans.shared.b16 {%0,%1,%2,%3}, [%4];"
                 : "=r"(r[0]), "=r"(r[1]), "=r"(r[2]), "=r"(r[3]) : "r"(addr));
}
__device__ __forceinline__ void mma_f16(float* c, const uint32_t* a,
                                        uint32_t b0, uint32_t b1) {
    asm volatile(
        "mma.sync.aligned.m16n8k16.row.col.f32.f16.f16.f32 "
        "{%0,%1,%2,%3}, {%4,%5,%6,%7}, {%8,%9}, {%0,%1,%2,%3};"
        : "+f"(c[0]), "+f"(c[1]), "+f"(c[2]), "+f"(c[3])
        : "r"(a[0]), "r"(a[1]), "r"(a[2]), "r"(a[3]), "r"(b0), "r"(b1));
}
__device__ __forceinline__ uint32_t h2u(float x, float y) {
    __half2 h = __floats2half2_rn(x, y);
    return *(uint32_t*)&h;
}

// ---------------- weight conversion ----------------
// vectorized fp32 -> fp16 (native layout preserved)
__global__ void cvt_half4_kernel(const float* __restrict__ src, __half* __restrict__ dst,
                                 int n4) {
    int i = blockIdx.x * blockDim.x + threadIdx.x;
    if (i >= n4) return;
    float4 v = ((const float4*)src)[i];
    __half2 a = __floats2half2_rn(v.x, v.y);
    __half2 b = __floats2half2_rn(v.z, v.w);
    uint2 u = make_uint2(*(uint32_t*)&a, *(uint32_t*)&b);
    ((uint2*)dst)[i] = u;
}
// transpose+convert (square 768x768, used for conv_w [N,K] -> [K,N])
__global__ void tr_half_kernel(const float* __restrict__ src, __half* __restrict__ dst,
                               int K, int N) {
    __shared__ float t[32][33];
    size_t off = (size_t)blockIdx.z * K * N;
    src += off; dst += off;
    int kb = blockIdx.y * 32, nb = blockIdx.x * 32;
    for (int i = threadIdx.y; i < 32; i += 8)
        t[i][threadIdx.x] = src[(size_t)(kb + i) * N + nb + threadIdx.x];
    __syncthreads();
    for (int i = threadIdx.y; i < 32; i += 8)
        dst[(size_t)(nb + i) * K + kb + threadIdx.x] = __float2half_rn(t[threadIdx.x][i]);
}

// ---------------- patchify -> half ----------------
__global__ void patch_kernel(const float* __restrict__ x, __half* __restrict__ xp) {
    int idx = blockIdx.x * blockDim.x + threadIdx.x;
    if (idx >= TOK * DMODEL) return;
    int t = idx / DMODEL;
    int f = idx - t * DMODEL;
    int b = t / NPATCH;
    int p = t - b * NPATCH;
    int gy = p / GRID_, gx = p - gy * GRID_;
    int c  = f >> 8;
    int py = (f >> 4) & 15;
    int px = f & 15;
    xp[idx] = __float2half_rn(
        x[(((size_t)b * 3 + c) * IMG + gy * PSZ + py) * IMG + gx * PSZ + px]);
}

// ---------------- FP16 mma.sync GEMM (B in [K,N] via ldmatrix.trans) ----------------
// OP 0: +bias -> HALF ; 1: +bias+res -> fp32 ; 2: +bias,GELU -> HALF ; 3: +bias+pos -> fp32
#define KCH  64
#define ASTR 72
#define BSTR 136                                  // 128 + 8 pad halfs
#define A_HALFS (128 * ASTR)                      // 9216
#define B_HALFS (KCH * BSTR)                      // 8704
#define STAGE_HALFS (A_HALFS + B_HALFS)           // 17920
#define STAGE_BYTES (STAGE_HALFS * 2)             // 35840
#define GSTAGES 3
#define GEMM_SMEM (GSTAGES * STAGE_BYTES)         // 107520

template <int OP>
__global__ void __launch_bounds__(128, 2)
gemm_fp16(const __half* __restrict__ A, const __half* __restrict__ B,
          const float* __restrict__ bias, const float* __restrict__ res,
          void* __restrict__ Cout, int M, int N, int K) {
    extern __shared__ __half sm[];
    const int tid = threadIdx.x;
    const int m0 = blockIdx.y * 128, n0 = blockIdx.x * 128;
    const int warp = tid >> 5, lane = tid & 31;
    const int wm = warp >> 1, wn = warp & 1;
    const int g = lane >> 2, tg = lane & 3;

    const uint32_t smb = smem_u32(sm);
    uint32_t aAddr[4], bAddr[4];
#pragma unroll
    for (int mi = 0; mi < 4; mi++)
        aAddr[mi] = smb + ((wm * 64 + mi * 16 + (lane & 15)) * ASTR +
                           ((lane >> 4) & 1) * 8) * 2;
    // trans B: addr row = k (lane&7) + ((lane>>3)&1)*8 ; col = n-tile + ((lane>>4)&1)*8
#pragma unroll
    for (int n2 = 0; n2 < 4; n2++)
        bAddr[n2] = smb + A_HALFS * 2 +
                    (((lane & 7) + ((lane >> 3) & 1) * 8) * BSTR +
                     wn * 64 + n2 * 16 + ((lane >> 4) & 1) * 8) * 2;

    float acc[4][8][4];
#pragma unroll
    for (int i = 0; i < 4; i++)
#pragma unroll
        for (int j = 0; j < 8; j++)
#pragma unroll
            for (int c = 0; c < 4; c++) acc[i][j][c] = 0.f;

    const int nIter = K >> 6;

    auto load_stage = [&](int it) {
        __half* As = sm + (it % GSTAGES) * STAGE_HALFS;
        __half* Bs = As + A_HALFS;
        int k0 = it * KCH;
        const __half* Ag = A + (size_t)m0 * K + k0;
        const __half* Bg = B + (size_t)k0 * N + n0;
#pragma unroll
        for (int i = 0; i < 8; i++) {             // A: 128 rows x 8 chunks of 8 halfs
            int idx = tid + i * 128;
            int r = idx >> 3, c = (idx & 7) * 8;
            cpasync16(&As[r * ASTR + c], Ag + (size_t)r * K + c);
        }
#pragma unroll
        for (int i = 0; i < 8; i++) {             // B: 64 k-rows x 16 chunks of 8 halfs
            int idx = tid + i * 128;
            int r = idx >> 4, c = (idx & 15) * 8;
            cpasync16(&Bs[r * BSTR + c], Bg + (size_t)r * N + c);
        }
        asm volatile("cp.async.commit_group;");
    };

    load_stage(0);

    for (int it = 0; it < nIter; it++) {
        if (it + 1 < nIter) {
            load_stage(it + 1);
            asm volatile("cp.async.wait_group 1;");
        } else {
            asm volatile("cp.async.wait_group 0;");
        }
        __syncthreads();

        uint32_t stOff = (uint32_t)((it % GSTAGES) * STAGE_BYTES);
#pragma unroll
        for (int kk = 0; kk < 4; kk++) {
            uint32_t a[4][4], b[4][4];
#pragma unroll
            for (int mi = 0; mi < 4; mi++) ldmx4(a[mi], aAddr[mi] + stOff + kk * 32);
#pragma unroll
            for (int n2 = 0; n2 < 4; n2++)
                ldmx4t(b[n2], bAddr[n2] + stOff + kk * 16 * BSTR * 2);
#pragma unroll
            for (int mi = 0; mi < 4; mi++)
#pragma unroll
                for (int n2 = 0; n2 < 4; n2++) {
                    mma_f16(acc[mi][n2 * 2 + 0], a[mi], b[n2][0], b[n2][1]);
                    mma_f16(acc[mi][n2 * 2 + 1], a[mi], b[n2][2], b[n2][3]);
                }
        }
    }

    // ---- epilogue ----
    float* Cf = (float*)Cout;
    __half* Ch = (__half*)Cout;
#pragma unroll
    for (int mi = 0; mi < 4; mi++) {
        int r0 = m0 + wm * 64 + mi * 16 + g;
#pragma unroll
        for (int ni = 0; ni < 8; ni++) {
            int n = n0 + wn * 64 + ni * 8 + tg * 2;
            float2 bi = *(const float2*)(bias + n);
#pragma unroll
            for (int half = 0; half < 2; half++) {
                int m = r0 + half * 8;
                float v0 = acc[mi][ni][half * 2 + 0] + bi.x;
                float v1 = acc[mi][ni][half * 2 + 1] + bi.y;
                if (OP == 1) {
                    float2 rv = *(const float2*)(res + (size_t)m * N + n);
                    v0 += rv.x; v1 += rv.y;
                }
                if (OP == 3) {
                    float2 rv = *(const float2*)(res + (size_t)(m % NPATCH) * N + n);
                    v0 += rv.x; v1 += rv.y;
                }
                if (OP == 2) {
                    v0 = 0.5f * v0 * (1.0f + erff(v0 * 0.70710678118654752f));
                    v1 = 0.5f * v1 * (1.0f + erff(v1 * 0.70710678118654752f));
                }
                if (OP == 0 || OP == 2) {
                    *(__half2*)(Ch + (size_t)m * N + n) = __floats2half2_rn(v0, v1);
                } else {
                    *(float2*)(Cf + (size_t)m * N + n) = make_float2(v0, v1);
                }
            }
        }
    }
}

// ---------------- attention: tensor-core flash-lite, one CTA per (b,h) ----------------
#define QSTR 72
#define VSTR 216
#define QS_OFF 0
#define KS_OFF (208 * QSTR)
#define VT_OFF (2 * 208 * QSTR)
#define SMEM_ATTN ((VT_OFF + 64 * VSTR) * 2)   // 87552 bytes

__global__ void __launch_bounds__(256, 1)
attn_kernel(const __half* __restrict__ qkv, __half* __restrict__ o) {
    extern __shared__ __half smh[];
    const int tid = threadIdx.x;
    const int bh = blockIdx.x;
    const int b = bh / NHEAD, hh = bh - b * NHEAD;
    const __half* base = qkv + (size_t)b * NPATCH * QKVN + hh * HDIM;

    for (int i = tid; i < 64 * VSTR / 8; i += 256)
        ((uint4*)(smh + VT_OFF))[i] = make_uint4(0u, 0u, 0u, 0u);
    __syncthreads();
    for (int i = tid; i < 208 * 8; i += 256) {
        int r = i >> 3, c = (i & 7) * 8;
        int row = r < NPATCH ? r : NPATCH - 1;
        const __half* src = base + (size_t)row * QKVN;
        *(uint4*)(smh + QS_OFF + r * QSTR + c) = *(const uint4*)(src + c);
        *(uint4*)(smh + KS_OFF + r * QSTR + c) = *(const uint4*)(src + DMODEL + c);
    }
    for (int i = tid; i < NPATCH * 8; i += 256) {
        int kidx = i >> 3, c8 = (i & 7) * 8;
        uint4 v = *(const uint4*)(base + (size_t)kidx * QKVN + 2 * DMODEL + c8);
        const __half* vh = (const __half*)&v;
#pragma unroll
        for (int d = 0; d < 8; d++)
            smh[VT_OFF + (c8 + d) * VSTR + kidx] = vh[d];
    }
    __syncthreads();

    const int warp = tid >> 5, lane = tid & 31;
    const int g = lane >> 2, tg = lane & 3;
    const uint32_t smb = smem_u32(smh);
    const uint32_t qsB = smb + QS_OFF * 2;
    const uint32_t ksB = smb + KS_OFF * 2;
    const uint32_t vtB = smb + VT_OFF * 2;

    const uint32_t aRow = ((lane & 15) * QSTR + ((lane >> 4) & 1) * 8) * 2;
    const uint32_t bRowK = (((lane & 7) + ((lane >> 4) & 1) * 8) * QSTR + ((lane >> 3) & 1) * 8) * 2;
    const uint32_t bRowV = (((lane & 7) + ((lane >> 4) & 1) * 8) * VSTR + ((lane >> 3) & 1) * 8) * 2;

    for (int qc = warp; qc < 13; qc += 8) {
        int q0 = qc * 16;
        uint32_t qa[4][4];
#pragma unroll
        for (int kk = 0; kk < 4; kk++)
            ldmx4(qa[kk], qsB + q0 * QSTR * 2 + aRow + kk * 32);

        float sacc[26][4];
#pragma unroll
        for (int j = 0; j < 26; j++)
#pragma unroll
            for (int c = 0; c < 4; c++) sacc[j][c] = 0.f;

#pragma unroll
        for (int n2 = 0; n2 < 13; n2++) {
#pragma unroll
            for (int kk = 0; kk < 4; kk++) {
                uint32_t bk[4];
                ldmx4(bk, ksB + n2 * 16 * QSTR * 2 + bRowK + kk * 32);
                mma_f16(sacc[n2 * 2 + 0], qa[kk], bk[0], bk[1]);
                mma_f16(sacc[n2 * 2 + 1], qa[kk], bk[2], bk[3]);
            }
        }

        float m0 = -1e30f, m1 = -1e30f;
#pragma unroll
        for (int j = 0; j < 25; j++) {
            bool v = (j < 24) || (tg < 2);
            if (v) {
                m0 = fmaxf(m0, fmaxf(sacc[j][0], sacc[j][1]));
                m1 = fmaxf(m1, fmaxf(sacc[j][2], sacc[j][3]));
            }
        }
        m0 = fmaxf(m0, __shfl_xor_sync(0xffffffffu, m0, 1));
        m0 = fmaxf(m0, __shfl_xor_sync(0xffffffffu, m0, 2));
        m1 = fmaxf(m1, __shfl_xor_sync(0xffffffffu, m1, 1));
        m1 = fmaxf(m1, __shfl_xor_sync(0xffffffffu, m1, 2));

        float l0 = 0.f, l1 = 0.f;
#pragma unroll
        for (int j = 0; j < 26; j++) {
            bool v = (j < 24) || (j == 24 && tg < 2);
            float e0 = v ? __expf(0.125f * (sacc[j][0] - m0)) : 0.f;
            float e1 = v ? __expf(0.125f * (sacc[j][1] - m0)) : 0.f;
            float e2 = v ? __expf(0.125f * (sacc[j][2] - m1)) : 0.f;
            float e3 = v ? __expf(0.125f * (sacc[j][3] - m1)) : 0.f;
            sacc[j][0] = e0; sacc[j][1] = e1; sacc[j][2] = e2; sacc[j][3] = e3;
            l0 += e0 + e1; l1 += e2 + e3;
        }
        l0 += __shfl_xor_sync(0xffffffffu, l0, 1);
        l0 += __shfl_xor_sync(0xffffffffu, l0, 2);
        l1 += __shfl_xor_sync(0xffffffffu, l1, 1);
        l1 += __shfl_xor_sync(0xffffffffu, l1, 2);
        float i0 = 1.f / l0, i1 = 1.f / l1;

        uint32_t pa[13][4];
#pragma unroll
        for (int nt = 0; nt < 13; nt++) {
            pa[nt][0] = h2u(sacc[2 * nt][0] * i0, sacc[2 * nt][1] * i0);
            pa[nt][1] = h2u(sacc[2 * nt][2] * i1, sacc[2 * nt][3] * i1);
            pa[nt][2] = h2u(sacc[2 * nt + 1][0] * i0, sacc[2 * nt + 1][1] * i0);
            pa[nt][3] = h2u(sacc[2 * nt + 1][2] * i1, sacc[2 * nt + 1][3] * i1);
        }

        float oacc[8][4];
#pragma unroll
        for (int j = 0; j < 8; j++)
#pragma unroll
            for (int c = 0; c < 4; c++) oacc[j][c] = 0.f;

#pragma unroll
        for (int dn2 = 0; dn2 < 4; dn2++) {
#pragma unroll
            for (int nt = 0; nt < 13; nt++) {
                uint32_t bv[4];
                ldmx4(bv, vtB + dn2 * 16 * VSTR * 2 + bRowV + nt * 32);
                mma_f16(oacc[dn2 * 2 + 0], pa[nt], bv[0], bv[1]);
                mma_f16(oacc[dn2 * 2 + 1], pa[nt], bv[2], bv[3]);
            }
        }

        int r0 = q0 + g, r1 = q0 + g + 8;
        __half* ob = o + (size_t)b * NPATCH * DMODEL + hh * HDIM;
#pragma unroll
        for (int j8 = 0; j8 < 8; j8++) {
            int col = j8 * 8 + 2 * tg;
            if (r0 < NPATCH)
                *(__half2*)(ob + (size_t)r0 * DMODEL + col) =
                    __floats2half2_rn(oacc[j8][0], oacc[j8][1]);
            if (r1 < NPATCH)
                *(__half2*)(ob + (size_t)r1 * DMODEL + col) =
                    __floats2half2_rn(oacc[j8][2], oacc[j8][3]);
        }
    }
}

// ---------------- layernorm: float4 vectorized, 192 threads/row ----------------
template <int HALF_OUT>
__global__ void ln_kernel(const float* __restrict__ x, const float* __restrict__ w,
                          const float* __restrict__ bb, void* __restrict__ y) {
    int t = blockIdx.x;
    int tid = threadIdx.x;                    // 192
    float4 v = ((const float4*)(x + (size_t)t * DMODEL))[tid];
    float s  = v.x + v.y + v.z + v.w;
    float ss = v.x * v.x + v.y * v.y + v.z * v.z + v.w * v.w;
    __shared__ float redS[6], redQ[6];
#pragma unroll
    for (int off = 16; off; off >>= 1) {
        s  += __shfl_xor_sync(0xffffffffu, s,  off);
        ss += __shfl_xor_sync(0xffffffffu, ss, off);
    }
    if ((tid & 31) == 0) { redS[tid >> 5] = s; redQ[tid >> 5] = ss; }
    __syncthreads();
    if (tid == 0) {
        float a = 0.f, b2 = 0.f;
#pragma unroll
        for (int i = 0; i < 6; i++) { a += redS[i]; b2 += redQ[i]; }
        float mean = a * (1.0f / DMODEL);
        float var = b2 * (1.0f / DMODEL) - mean * mean;
        redS[0] = mean;
        redQ[0] = rsqrtf(var + 1e-5f);
    }
    __syncthreads();
    float mean = redS[0], rstd = redQ[0];
    float4 wv = ((const float4*)w)[tid];
    float4 bv = ((const float4*)bb)[tid];
    float o0 = (v.x - mean) * rstd * wv.x + bv.x;
    float o1 = (v.y - mean) * rstd * wv.y + bv.y;
    float o2 = (v.z - mean) * rstd * wv.z + bv.z;
    float o3 = (v.w - mean) * rstd * wv.w + bv.w;
    if (HALF_OUT) {
        __half2 a = __floats2half2_rn(o0, o1);
        __half2 b = __floats2half2_rn(o2, o3);
        ((uint2*)((__half*)y + (size_t)t * DMODEL))[tid] =
            make_uint2(*(uint32_t*)&a, *(uint32_t*)&b);
    } else {
        ((float4*)((float*)y + (size_t)t * DMODEL))[tid] = make_float4(o0, o1, o2, o3);
    }
}

// ---------------- launch ----------------
extern "C" void kernel_launch(void* const* d_in, const int* in_sizes, int n_in,
                              void* d_out, int out_size) {
    const float* x      = (const float*)d_in[0];
    const float* conv_w = (const float*)d_in[1];
    const float* conv_b = (const float*)d_in[2];
    const float* pos    = (const float*)d_in[3];
    const float* ln1w   = (const float*)d_in[4];
    const float* ln1b   = (const float*)d_in[5];
    const float* qkvw   = (const float*)d_in[6];
    const float* qkvb   = (const float*)d_in[7];
    const float* projw  = (const float*)d_in[8];
    const float* projb  = (const float*)d_in[9];
    const float* ln2w   = (const float*)d_in[10];
    const float* ln2b   = (const float*)d_in[11];
    const float* f1w    = (const float*)d_in[12];
    const float* f1b    = (const float*)d_in[13];
    const float* f2w    = (const float*)d_in[14];
    const float* f2b    = (const float*)d_in[15];
    const float* lnfw   = (const float*)d_in[16];
    const float* lnfb   = (const float*)d_in[17];
    float* out = (float*)d_out;

    float* h;
    __half *qkv, *xp, *y, *o, *act, *wpe, *rqkvw, *rprojw, *rf1w, *rf2w;
    cudaGetSymbolAddress((void**)&h,   g_h);
    cudaGetSymbolAddress((void**)&qkv, h_qkv);
    cudaGetSymbolAddress((void**)&xp,  h_xp);
    cudaGetSymbolAddress((void**)&y,   h_y);
    cudaGetSymbolAddress((void**)&o,   h_o);
    cudaGetSymbolAddress((void**)&act, h_act);
    cudaGetSymbolAddress((void**)&wpe, w_pe);
    cudaGetSymbolAddress((void**)&rqkvw,  w_qkv);
    cudaGetSymbolAddress((void**)&rprojw, w_proj);
    cudaGetSymbolAddress((void**)&rf1w,   w_f1);
    cudaGetSymbolAddress((void**)&rf2w,   w_f2);

    cudaFuncSetAttribute(attn_kernel, cudaFuncAttributeMaxDynamicSharedMemorySize, SMEM_ATTN);
    cudaFuncSetAttribute(gemm_fp16<0>, cudaFuncAttributeMaxDynamicSharedMemorySize, GEMM_SMEM);
    cudaFuncSetAttribute(gemm_fp16<1>, cudaFuncAttributeMaxDynamicSharedMemorySize, GEMM_SMEM);
    cudaFuncSetAttribute(gemm_fp16<2>, cudaFuncAttributeMaxDynamicSharedMemorySize, GEMM_SMEM);
    cudaFuncSetAttribute(gemm_fp16<3>, cudaFuncAttributeMaxDynamicSharedMemorySize, GEMM_SMEM);

    // weights -> half, native [K,N] layout (no transpose); conv_w [N,K] -> [K,N]
    {
        int n4;
        n4 = NLAYER * DMODEL * QKVN   / 4; cvt_half4_kernel<<<(n4 + 255) / 256, 256>>>(qkvw,  rqkvw,  n4);
        n4 = NLAYER * DMODEL * DMODEL / 4; cvt_half4_kernel<<<(n4 + 255) / 256, 256>>>(projw, rprojw, n4);
        n4 = NLAYER * DMODEL * HIDDEN / 4; cvt_half4_kernel<<<(n4 + 255) / 256, 256>>>(f1w,   rf1w,   n4);
        n4 = NLAYER * HIDDEN * DMODEL / 4; cvt_half4_kernel<<<(n4 + 255) / 256, 256>>>(f2w,   rf2w,   n4);
        tr_half_kernel<<<dim3(24, 24, 1), dim3(32, 8)>>>(conv_w, wpe, DMODEL, DMODEL);
    }

    // patchify + patch-embed GEMM (+bias +pos_embed)
    patch_kernel<<<(TOK * DMODEL + 255) / 256, 256>>>(x, xp);
    gemm_fp16<3><<<dim3(DMODEL / 128, TOK / 128), 128, GEMM_SMEM>>>(
        xp, wpe, conv_b, pos, h, TOK, DMODEL, DMODEL);

    for (int l = 0; l < NLAYER; l++) {
        ln_kernel<1><<<TOK, 192>>>(h, ln1w + (size_t)l * DMODEL, ln1b + (size_t)l * DMODEL, y);
        gemm_fp16<0><<<dim3(QKVN / 128, TOK / 128), 128, GEMM_SMEM>>>(
            y, rqkvw + (size_t)l * DMODEL * QKVN, qkvb + (size_t)l * QKVN, nullptr, qkv,
            TOK, QKVN, DMODEL);
        attn_kernel<<<BATCH * NHEAD, 256, SMEM_ATTN>>>(qkv, o);
        gemm_fp16<1><<<dim3(DMODEL / 128, TOK / 128), 128, GEMM_SMEM>>>(
            o, rprojw + (size_t)l * DMODEL * DMODEL, projb + (size_t)l * DMODEL, h, h,
            TOK, DMODEL, DMODEL);
        ln_kernel<1><<<TOK, 192>>>(h, ln2w + (size_t)l * DMODEL, ln2b + (size_t)l * DMODEL, y);
        gemm_fp16<2><<<dim3(HIDDEN / 128, TOK / 128), 128, GEMM_SMEM>>>(
            y, rf1w + (size_t)l * DMODEL * HIDDEN, f1b + (size_t)l * HIDDEN, nullptr, act,
            TOK, HIDDEN, DMODEL);
        gemm_fp16<1><<<dim3(DMODEL / 128, TOK / 128), 128, GEMM_SMEM>>>(
            act, rf2w + (size_t)l * HIDDEN * DMODEL, f2b + (size_t)l * DMODEL, h, h,
            TOK, DMODEL, HIDDEN);
    }
    ln_kernel<0><<<TOK, 192>>>(h, lnfw, lnfb, out);
}